// round 1
// baseline (speedup 1.0000x reference)
#include <cuda_runtime.h>
#include <math.h>

#define S_LEN   2048
#define BATCH   2
#define NHEADS  32
#define NKV     8
#define HDIM    128
#define HID     4096
#define KVDIM   1024
#define M_ROWS  4096   // B*S
#define WINDOW  512    // SLIDING_WINDOW // 2

// -------- scratch (static device globals; no allocation allowed) ----------
__device__ float g_Q[(size_t)BATCH * NHEADS * S_LEN * HDIM]; // 64 MB [b,h,s,d]
__device__ float g_K[(size_t)BATCH * NKV   * S_LEN * HDIM];  // 16 MB
__device__ float g_V[(size_t)BATCH * NKV   * S_LEN * HDIM];  // 16 MB
__device__ float g_O[(size_t)BATCH * NHEADS * S_LEN * HDIM]; // 64 MB

// ---------------------------------------------------------------------------
// SGEMM: C[M,N] = A[M,K] @ B[K,N], fp32, 128x128x16 tiles, 256 threads, 8x8/thr
// AMODE 0: A row-major [M,K].  AMODE 1: A is g_O in [b,h,s,d] layout, logical
//          A[row = b*S+s][k = h*128+d].
// CMODE 0: C row-major [M,N].  CMODE 1: scatter C to [b,h,s,d] (nH heads).
// ---------------------------------------------------------------------------
template<int AMODE, int CMODE>
__global__ void __launch_bounds__(256) sgemm_kernel(
    const float* __restrict__ A, const float* __restrict__ B,
    float* __restrict__ C, int M, int N, int K, int nH)
{
    __shared__ float As[16][128];   // transposed: As[k][m]
    __shared__ float Bs[16][128];

    const int tid = threadIdx.x;
    const int tx  = tid & 15;
    const int ty  = tid >> 4;
    const int rowBase = blockIdx.y * 128;
    const int colBase = blockIdx.x * 128;

    float acc[8][8];
#pragma unroll
    for (int i = 0; i < 8; i++)
#pragma unroll
        for (int j = 0; j < 8; j++) acc[i][j] = 0.f;

    for (int k0 = 0; k0 < K; k0 += 16) {
#pragma unroll
        for (int it = 0; it < 2; it++) {
            int s  = tid + it * 256;          // 0..511 float4 slots for A
            int r  = s >> 2;                  // 0..127
            int kq = (s & 3) << 2;            // 0,4,8,12
            int grow = rowBase + r;
            int gk   = k0 + kq;
            float4 av;
            if (AMODE == 0) {
                av = *reinterpret_cast<const float4*>(A + (size_t)grow * K + gk);
            } else {
                int b = grow >> 11, srow = grow & 2047;
                int h = gk >> 7,   d   = gk & 127;
                size_t idx = (((size_t)(b * NHEADS + h)) * S_LEN + srow) * HDIM + d;
                av = *reinterpret_cast<const float4*>(A + idx);
            }
            As[kq + 0][r] = av.x;
            As[kq + 1][r] = av.y;
            As[kq + 2][r] = av.z;
            As[kq + 3][r] = av.w;

            int kr = s >> 5;                  // 0..15
            int c  = (s & 31) << 2;           // 0..124
            float4 bv = *reinterpret_cast<const float4*>(
                B + (size_t)(k0 + kr) * N + colBase + c);
            *reinterpret_cast<float4*>(&Bs[kr][c]) = bv;
        }
        __syncthreads();

#pragma unroll
        for (int kk = 0; kk < 16; kk++) {
            float a[8], bb[8];
            *reinterpret_cast<float4*>(a)      = *reinterpret_cast<float4*>(&As[kk][ty * 8]);
            *reinterpret_cast<float4*>(a + 4)  = *reinterpret_cast<float4*>(&As[kk][ty * 8 + 4]);
            *reinterpret_cast<float4*>(bb)     = *reinterpret_cast<float4*>(&Bs[kk][tx * 8]);
            *reinterpret_cast<float4*>(bb + 4) = *reinterpret_cast<float4*>(&Bs[kk][tx * 8 + 4]);
#pragma unroll
            for (int i = 0; i < 8; i++)
#pragma unroll
                for (int j = 0; j < 8; j++)
                    acc[i][j] = fmaf(a[i], bb[j], acc[i][j]);
        }
        __syncthreads();
    }

#pragma unroll
    for (int i = 0; i < 8; i++) {
        int grow = rowBase + ty * 8 + i;
#pragma unroll
        for (int j4 = 0; j4 < 2; j4++) {
            int gcol = colBase + tx * 8 + j4 * 4;
            float4 v = make_float4(acc[i][j4*4+0], acc[i][j4*4+1],
                                   acc[i][j4*4+2], acc[i][j4*4+3]);
            if (CMODE == 0) {
                *reinterpret_cast<float4*>(C + (size_t)grow * N + gcol) = v;
            } else {
                int b = grow >> 11, srow = grow & 2047;
                int h = gcol >> 7, d    = gcol & 127;
                size_t idx = (((size_t)(b * nH + h)) * S_LEN + srow) * HDIM + d;
                *reinterpret_cast<float4*>(C + idx) = v;
            }
        }
    }
}

// ---------------------------------------------------------------------------
// RoPE in place on [B, nH, S, 128]; also folds in `scale` (1/sqrt(hd) for Q).
// Pair (i, i+64): x1' = x1*cos - x2*sin ; x2' = x2*cos + x1*sin, ang = s*theta^(-i/64)
// ---------------------------------------------------------------------------
__global__ void rope_kernel(float* __restrict__ X, int nH, float scale, int total)
{
    int idx = blockIdx.x * blockDim.x + threadIdx.x;
    if (idx >= total) return;
    int i  = idx & 63;
    int s  = (idx >> 6) & (S_LEN - 1);
    int bh = idx >> 17;                        // / (64*2048)
    size_t base = ((size_t)bh * S_LEN + s) * HDIM;
    float inv_freq = expf(-(float)i * (logf(10000.0f) / 64.0f));
    float ang = (float)s * inv_freq;
    float c = cosf(ang), sn = sinf(ang);
    float x1 = X[base + i];
    float x2 = X[base + i + 64];
    X[base + i]       = (x1 * c - x2 * sn) * scale;
    X[base + i + 64]  = (x2 * c + x1 * sn) * scale;
}

// ---------------------------------------------------------------------------
// Flash attention, fp32. Block = (qtile[64], head, batch). 256 threads.
// Key tiles kt in [max(0, qtile-8), qtile] (window lookback 512).
// Smem: Qt[128][68] (d-major), Kt[128][68], Vs[64][132], Ps[64][68], f/l[64].
// ---------------------------------------------------------------------------
__global__ void __launch_bounds__(256, 1) attn_kernel()
{
    extern __shared__ float sm[];
    float* Qt   = sm;                    // 128*68
    float* Kt   = Qt + 128 * 68;         // 128*68
    float* Vs   = Kt + 128 * 68;         // 64*132
    float* Ps   = Vs + 64 * 132;         // 64*68
    float* f_sh = Ps + 64 * 68;          // 64
    float* l_sh = f_sh + 64;             // 64

    const int tid   = threadIdx.x;
    const int qtile = blockIdx.x;
    const int h     = blockIdx.y;
    const int b     = blockIdx.z;
    const int hk    = h >> 2;            // GQA: 4 q-heads per kv-head
    const int q0    = qtile * 64;

    const float* Qg = g_Q + (((size_t)(b * NHEADS + h)) * S_LEN + q0) * HDIM;
    const float* Kg = g_K + ((size_t)(b * NKV + hk)) * S_LEN * HDIM;
    const float* Vg = g_V + ((size_t)(b * NKV + hk)) * S_LEN * HDIM;

    // Load Q tile transposed: Qt[d][q]
#pragma unroll
    for (int it = 0; it < 8; it++) {
        int slot = tid + it * 256;       // 2048 float4 slots
        int r  = slot >> 5;              // q row 0..63
        int c4 = slot & 31;
        float4 v = *reinterpret_cast<const float4*>(Qg + (size_t)r * HDIM + c4 * 4);
        Qt[(c4 * 4 + 0) * 68 + r] = v.x;
        Qt[(c4 * 4 + 1) * 68 + r] = v.y;
        Qt[(c4 * 4 + 2) * 68 + r] = v.z;
        Qt[(c4 * 4 + 3) * 68 + r] = v.w;
    }

    const int tx = tid & 15;
    const int ty = tid >> 4;
    const int qy = ty * 4;               // 4 query rows for this thread
    const int kx = tx * 4;               // 4 key cols (S phase)
    const int dx = tx * 8;               // 8 dims (PV phase)

    float accO[4][8];
#pragma unroll
    for (int i = 0; i < 4; i++)
#pragma unroll
        for (int j = 0; j < 8; j++) accO[i][j] = 0.f;

    const int srow  = tid >> 2;          // row owned by this 4-lane group
    const int spart = tid & 3;
    float m_run = -1e30f;
    float l_run = 0.f;

    int kt_lo = qtile - 8; if (kt_lo < 0) kt_lo = 0;

    for (int kt = kt_lo; kt <= qtile; kt++) {
        const int k0 = kt * 64;
        // Load K (transposed) and V tiles
#pragma unroll
        for (int it = 0; it < 8; it++) {
            int slot = tid + it * 256;
            int r  = slot >> 5;
            int c4 = slot & 31;
            float4 kv = *reinterpret_cast<const float4*>(Kg + (size_t)(k0 + r) * HDIM + c4 * 4);
            Kt[(c4 * 4 + 0) * 68 + r] = kv.x;
            Kt[(c4 * 4 + 1) * 68 + r] = kv.y;
            Kt[(c4 * 4 + 2) * 68 + r] = kv.z;
            Kt[(c4 * 4 + 3) * 68 + r] = kv.w;
            float4 vv = *reinterpret_cast<const float4*>(Vg + (size_t)(k0 + r) * HDIM + c4 * 4);
            *reinterpret_cast<float4*>(&Vs[r * 132 + c4 * 4]) = vv;
        }
        __syncthreads();

        // S = Q K^T (Q pre-scaled by 1/sqrt(hd))
        float sc[4][4];
#pragma unroll
        for (int i = 0; i < 4; i++)
#pragma unroll
            for (int j = 0; j < 4; j++) sc[i][j] = 0.f;
#pragma unroll 4
        for (int d = 0; d < 128; d++) {
            float a[4], bb[4];
            *reinterpret_cast<float4*>(a)  = *reinterpret_cast<float4*>(&Qt[d * 68 + qy]);
            *reinterpret_cast<float4*>(bb) = *reinterpret_cast<float4*>(&Kt[d * 68 + kx]);
#pragma unroll
            for (int i = 0; i < 4; i++)
#pragma unroll
                for (int j = 0; j < 4; j++)
                    sc[i][j] = fmaf(a[i], bb[j], sc[i][j]);
        }
        // Mask (causal + sliding window) and stage raw scores
#pragma unroll
        for (int i = 0; i < 4; i++) {
            int gi = q0 + qy + i;
#pragma unroll
            for (int j = 0; j < 4; j++) {
                int gj = k0 + kx + j;
                bool ok = (gj <= gi) && (gi - gj <= WINDOW);
                Ps[(qy + i) * 68 + kx + j] = ok ? sc[i][j] : -1e30f;
            }
        }
        __syncthreads();

        // Streaming softmax: 4 lanes per row
        float vals[16];
        float local_max = -1e30f;
#pragma unroll
        for (int u = 0; u < 16; u++) {
            vals[u] = Ps[srow * 68 + spart * 16 + u];
            local_max = fmaxf(local_max, vals[u]);
        }
        local_max = fmaxf(local_max, __shfl_xor_sync(0xffffffffu, local_max, 1));
        local_max = fmaxf(local_max, __shfl_xor_sync(0xffffffffu, local_max, 2));
        float m_new = fmaxf(m_run, local_max);
        float fac   = __expf(m_run - m_new);
        float psum  = 0.f;
#pragma unroll
        for (int u = 0; u < 16; u++) {
            float p = (vals[u] > -1e29f) ? __expf(vals[u] - m_new) : 0.f;
            Ps[srow * 68 + spart * 16 + u] = p;
            psum += p;
        }
        psum += __shfl_xor_sync(0xffffffffu, psum, 1);
        psum += __shfl_xor_sync(0xffffffffu, psum, 2);
        l_run = l_run * fac + psum;
        m_run = m_new;
        if (spart == 0) f_sh[srow] = fac;
        __syncthreads();

        // Rescale and accumulate O += P @ V
#pragma unroll
        for (int i = 0; i < 4; i++) {
            float f = f_sh[qy + i];
#pragma unroll
            for (int j = 0; j < 8; j++) accO[i][j] *= f;
        }
#pragma unroll 2
        for (int kk = 0; kk < 64; kk++) {
            float v[8];
            *reinterpret_cast<float4*>(v)     = *reinterpret_cast<float4*>(&Vs[kk * 132 + dx]);
            *reinterpret_cast<float4*>(v + 4) = *reinterpret_cast<float4*>(&Vs[kk * 132 + dx + 4]);
#pragma unroll
            for (int i = 0; i < 4; i++) {
                float p = Ps[(qy + i) * 68 + kk];
#pragma unroll
                for (int j = 0; j < 8; j++)
                    accO[i][j] = fmaf(p, v[j], accO[i][j]);
            }
        }
        __syncthreads();
    }

    if (spart == 0) l_sh[srow] = l_run;
    __syncthreads();

    float* Og = g_O + (((size_t)(b * NHEADS + h)) * S_LEN + q0) * HDIM;
#pragma unroll
    for (int i = 0; i < 4; i++) {
        float inv_l = 1.0f / l_sh[qy + i];
        float4 o0 = make_float4(accO[i][0] * inv_l, accO[i][1] * inv_l,
                                accO[i][2] * inv_l, accO[i][3] * inv_l);
        float4 o1 = make_float4(accO[i][4] * inv_l, accO[i][5] * inv_l,
                                accO[i][6] * inv_l, accO[i][7] * inv_l);
        *reinterpret_cast<float4*>(Og + (size_t)(qy + i) * HDIM + dx)     = o0;
        *reinterpret_cast<float4*>(Og + (size_t)(qy + i) * HDIM + dx + 4) = o1;
    }
}

// ---------------------------------------------------------------------------
extern "C" void kernel_launch(void* const* d_in, const int* in_sizes, int n_in,
                              void* d_out, int out_size)
{
    (void)in_sizes; (void)n_in; (void)out_size;
    const float* hidden = (const float*)d_in[0];
    const float* Wq     = (const float*)d_in[1];
    const float* Wk     = (const float*)d_in[2];
    const float* Wv     = (const float*)d_in[3];
    const float* Wo     = (const float*)d_in[4];
    float* out          = (float*)d_out;

    float* q; cudaGetSymbolAddress((void**)&q, g_Q);
    float* k; cudaGetSymbolAddress((void**)&k, g_K);
    float* v; cudaGetSymbolAddress((void**)&v, g_V);
    float* o; cudaGetSymbolAddress((void**)&o, g_O);

    // QKV projections (epilogue scatters to [b,h,s,d])
    {
        dim3 gq(HID / 128, M_ROWS / 128);
        sgemm_kernel<0, 1><<<gq, 256>>>(hidden, Wq, q, M_ROWS, HID, HID, NHEADS);
        dim3 gkv(KVDIM / 128, M_ROWS / 128);
        sgemm_kernel<0, 1><<<gkv, 256>>>(hidden, Wk, k, M_ROWS, KVDIM, HID, NKV);
        sgemm_kernel<0, 1><<<gkv, 256>>>(hidden, Wv, v, M_ROWS, KVDIM, HID, NKV);
    }

    // RoPE (Q also gets the 1/sqrt(hd) softmax scale folded in)
    {
        int totQ = BATCH * NHEADS * S_LEN * 64;
        int totK = BATCH * NKV * S_LEN * 64;
        float qscale = 1.0f / sqrtf((float)HDIM);
        rope_kernel<<<(totQ + 255) / 256, 256>>>(q, NHEADS, qscale, totQ);
        rope_kernel<<<(totK + 255) / 256, 256>>>(k, NKV, 1.0f, totK);
    }

    // Attention
    {
        size_t smem = (size_t)(128 * 68 * 2 + 64 * 132 + 64 * 68 + 128) * sizeof(float);
        cudaFuncSetAttribute(attn_kernel,
                             cudaFuncAttributeMaxDynamicSharedMemorySize, (int)smem);
        dim3 g(S_LEN / 64, NHEADS, BATCH);
        attn_kernel<<<g, 256, smem>>>();
    }

    // Output projection (gathers A from [b,h,s,d])
    {
        dim3 go(HID / 128, M_ROWS / 128);
        sgemm_kernel<1, 0><<<go, 256>>>(o, Wo, out, M_ROWS, HID, HID, NHEADS);
    }
}

// round 3
// speedup vs baseline: 1.5463x; 1.5463x over previous
#include <cuda_runtime.h>
#include <cuda_bf16.h>
#include <math.h>
#include <stdint.h>

#define S_LEN   2048
#define BATCH   2
#define NHEADS  32
#define NKV     8
#define HDIM    128
#define HID     4096
#define KVDIM   1024
#define M_ROWS  4096   // B*S
#define WINDOW  512    // SLIDING_WINDOW // 2
#define GK      4096   // GEMM K (always 4096 here)
#define NC      (GK/64)

// ======================== scratch buffers ==================================
__device__ float g_Q[(size_t)BATCH * NHEADS * S_LEN * HDIM];
__device__ float g_K[(size_t)BATCH * NKV   * S_LEN * HDIM];
__device__ float g_V[(size_t)BATCH * NKV   * S_LEN * HDIM];
__device__ float g_O[(size_t)BATCH * NHEADS * S_LEN * HDIM];

__device__ __nv_bfloat16 g_Xhi[(size_t)M_ROWS * HID];
__device__ __nv_bfloat16 g_Xlo[(size_t)M_ROWS * HID];
__device__ __nv_bfloat16 g_WqThi[(size_t)HID * HID];
__device__ __nv_bfloat16 g_WqTlo[(size_t)HID * HID];
__device__ __nv_bfloat16 g_WkThi[(size_t)KVDIM * HID];
__device__ __nv_bfloat16 g_WkTlo[(size_t)KVDIM * HID];
__device__ __nv_bfloat16 g_WvThi[(size_t)KVDIM * HID];
__device__ __nv_bfloat16 g_WvTlo[(size_t)KVDIM * HID];
__device__ __nv_bfloat16 g_WoThi[(size_t)HID * HID];
__device__ __nv_bfloat16 g_WoTlo[(size_t)HID * HID];
__device__ __nv_bfloat16 g_Ohi[(size_t)M_ROWS * HID];
__device__ __nv_bfloat16 g_Olo[(size_t)M_ROWS * HID];

// ======================= low-level helpers =================================
__device__ __forceinline__ uint32_t smem_u32(const void* p) {
    uint32_t a;
    asm("{ .reg .u64 t; cvta.to.shared.u64 t, %1; cvt.u32.u64 %0, t; }"
        : "=r"(a) : "l"(p));
    return a;
}

__device__ __forceinline__ void cpasync16(uint32_t saddr, const void* g) {
    asm volatile("cp.async.cg.shared.global [%0], [%1], 16;"
                 :: "r"(saddr), "l"(g) : "memory");
}

#define SWZ(o) ((o) ^ (((o) >> 3) & 0x70))

__device__ __forceinline__ void ldmx4(uint32_t* r, uint32_t addr) {
    asm volatile("ldmatrix.sync.aligned.m8n8.x4.shared.b16 {%0,%1,%2,%3}, [%4];"
                 : "=r"(r[0]), "=r"(r[1]), "=r"(r[2]), "=r"(r[3]) : "r"(addr));
}
__device__ __forceinline__ void ldmx2(uint32_t* r, uint32_t addr) {
    asm volatile("ldmatrix.sync.aligned.m8n8.x2.shared.b16 {%0,%1}, [%2];"
                 : "=r"(r[0]), "=r"(r[1]) : "r"(addr));
}
__device__ __forceinline__ void mma16816(float* d, const uint32_t* a, const uint32_t* b) {
    asm volatile("mma.sync.aligned.m16n8k16.row.col.f32.bf16.bf16.f32 "
                 "{%0,%1,%2,%3}, {%4,%5,%6,%7}, {%8,%9}, {%0,%1,%2,%3};"
                 : "+f"(d[0]), "+f"(d[1]), "+f"(d[2]), "+f"(d[3])
                 : "r"(a[0]), "r"(a[1]), "r"(a[2]), "r"(a[3]),
                   "r"(b[0]), "r"(b[1]));
}

// ===================== fp32 -> bf16 hi/lo split kernels ====================
__device__ __forceinline__ void split1(float f, __nv_bfloat16& h, __nv_bfloat16& l) {
    h = __float2bfloat16_rn(f);
    l = __float2bfloat16_rn(f - __bfloat162float(h));
}

__global__ void split_rowmajor_kernel(const float* __restrict__ X,
                                      __nv_bfloat16* __restrict__ hi,
                                      __nv_bfloat16* __restrict__ lo, int n4)
{
    int i = blockIdx.x * blockDim.x + threadIdx.x;
    if (i >= n4) return;
    float4 v = reinterpret_cast<const float4*>(X)[i];
    __nv_bfloat16 h0, h1, h2, h3, l0, l1, l2, l3;
    split1(v.x, h0, l0); split1(v.y, h1, l1);
    split1(v.z, h2, l2); split1(v.w, h3, l3);
    __nv_bfloat162* hp = reinterpret_cast<__nv_bfloat162*>(hi) + 2 * i;
    __nv_bfloat162* lp = reinterpret_cast<__nv_bfloat162*>(lo) + 2 * i;
    hp[0] = __halves2bfloat162(h0, h1); hp[1] = __halves2bfloat162(h2, h3);
    lp[0] = __halves2bfloat162(l0, l1); lp[1] = __halves2bfloat162(l2, l3);
}

// W [K, N] fp32  ->  T [N, K] bf16 hi/lo
__global__ void transpose_split_kernel(const float* __restrict__ W,
                                       __nv_bfloat16* __restrict__ hi,
                                       __nv_bfloat16* __restrict__ lo,
                                       int K, int N)
{
    __shared__ float t[32][33];
    int k0 = blockIdx.y * 32, n0 = blockIdx.x * 32;
    int c = threadIdx.x & 31, r = threadIdx.x >> 5;   // 256 thr: r 0..7
#pragma unroll
    for (int p = 0; p < 32; p += 8)
        t[r + p][c] = W[(size_t)(k0 + r + p) * N + n0 + c];
    __syncthreads();
#pragma unroll
    for (int p = 0; p < 32; p += 8) {
        float f = t[c][r + p];
        __nv_bfloat16 h, l;
        split1(f, h, l);
        size_t o = (size_t)(n0 + r + p) * K + k0 + c;
        hi[o] = h; lo[o] = l;
    }
}

// g_O [b,h,s,d] fp32 -> row-major [m=b*S+s, k=h*128+d] bf16 hi/lo
__global__ void splitO_kernel(const float* __restrict__ O,
                              __nv_bfloat16* __restrict__ hi,
                              __nv_bfloat16* __restrict__ lo, int n4)
{
    int i = blockIdx.x * blockDim.x + threadIdx.x;
    if (i >= n4) return;
    int e = i * 4;
    int m = e >> 12, col = e & 4095;
    int h = col >> 7, d = col & 127;
    int b = m >> 11, s = m & 2047;
    float4 v = *reinterpret_cast<const float4*>(
        O + ((((size_t)(b * NHEADS + h)) * S_LEN + s) * HDIM + d));
    __nv_bfloat16 h0, h1, h2, h3, l0, l1, l2, l3;
    split1(v.x, h0, l0); split1(v.y, h1, l1);
    split1(v.z, h2, l2); split1(v.w, h3, l3);
    __nv_bfloat162* hp = reinterpret_cast<__nv_bfloat162*>(hi) + 2 * i;
    __nv_bfloat162* lp = reinterpret_cast<__nv_bfloat162*>(lo) + 2 * i;
    hp[0] = __halves2bfloat162(h0, h1); hp[1] = __halves2bfloat162(h2, h3);
    lp[0] = __halves2bfloat162(l0, l1); lp[1] = __halves2bfloat162(l2, l3);
}

// =================== mma.sync bf16-split GEMM ==============================
// C[M,N] = (Ahi+Alo)[M,GK] @ (Bhi+Blo)^T, B stored [N,GK] K-major.
// CTA 128x128, 256 threads (8 warps, 2x4), warp tile 64x32, K-chunk 64.
// 3-stage cp.async pipeline; SW128 swizzled tiles; ldmatrix + mma.m16n8k16.
// CMODE 0: C row-major [M,N]. CMODE 1: scatter C to [b,h,s,d] (nH heads).
#define TILE_BYTES  16384              // 128 rows x 128B (64 bf16)
#define STAGE_BYTES (4 * TILE_BYTES)   // Ahi, Alo, Bhi, Blo
#define GEMM_SMEM   (3 * STAGE_BYTES)  // 192 KB

__device__ __forceinline__ void load_stage_gemm(
    uint32_t stage_base, int tid, int mBase, int nBase, int kb,
    const __nv_bfloat16* __restrict__ Ahi, const __nv_bfloat16* __restrict__ Alo,
    const __nv_bfloat16* __restrict__ Bhi, const __nv_bfloat16* __restrict__ Blo)
{
#pragma unroll
    for (int u = 0; u < 4; ++u) {
        int unit = tid + u * 256;           // 0..1023 (16B units in a tile)
        int r = unit >> 3, c16 = unit & 7;
        uint32_t soff = (uint32_t)(r * 128 + c16 * 16);
        uint32_t sw = SWZ(soff);
        size_t ga = (size_t)(mBase + r) * GK + kb + c16 * 8;  // 8 bf16 = 16B
        size_t gb = (size_t)(nBase + r) * GK + kb + c16 * 8;
        cpasync16(stage_base + sw,                  Ahi + ga);
        cpasync16(stage_base + TILE_BYTES + sw,     Alo + ga);
        cpasync16(stage_base + 2 * TILE_BYTES + sw, Bhi + gb);
        cpasync16(stage_base + 3 * TILE_BYTES + sw, Blo + gb);
    }
    asm volatile("cp.async.commit_group;" ::: "memory");
}

__global__ void __launch_bounds__(256, 1) mma_gemm_kernel(
    const __nv_bfloat16* __restrict__ Ahi, const __nv_bfloat16* __restrict__ Alo,
    const __nv_bfloat16* __restrict__ Bhi, const __nv_bfloat16* __restrict__ Blo,
    float* __restrict__ C, int N, int nH, int CMODE)
{
    extern __shared__ __align__(1024) char smem_raw[];
    const uint32_t sbase = smem_u32(smem_raw);
    const int tid  = threadIdx.x;
    const int wid  = tid >> 5, lane = tid & 31;
    const int wm   = wid >> 2;            // 0..1  (64 rows each)
    const int wn   = wid & 3;             // 0..3  (32 cols each)
    const int mBase = blockIdx.y * 128;
    const int nBase = blockIdx.x * 128;

    float acc[4][4][4];
#pragma unroll
    for (int mt = 0; mt < 4; mt++)
#pragma unroll
        for (int nt = 0; nt < 4; nt++)
#pragma unroll
            for (int e = 0; e < 4; e++) acc[mt][nt][e] = 0.f;

    // prologue: stages 0..2 <- chunks 0..2
    load_stage_gemm(sbase + 0 * STAGE_BYTES, tid, mBase, nBase, 0,   Ahi, Alo, Bhi, Blo);
    load_stage_gemm(sbase + 1 * STAGE_BYTES, tid, mBase, nBase, 64,  Ahi, Alo, Bhi, Blo);
    load_stage_gemm(sbase + 2 * STAGE_BYTES, tid, mBase, nBase, 128, Ahi, Alo, Bhi, Blo);

    // per-lane fragment coordinates
    const int aRow = wm * 64 + (lane & 15);        // + mt*16
    const int aK8  = (lane >> 4);                  // 0/1 -> +8 k
    const int bRow = wn * 32 + (lane & 7);         // + nt*8
    const int bK8  = ((lane >> 3) & 1);            // 0/1 -> +8 k

    for (int c2 = 0; c2 < NC; ++c2) {
        if (c2 + 2 < NC)      asm volatile("cp.async.wait_group 2;" ::: "memory");
        else if (c2 + 1 < NC) asm volatile("cp.async.wait_group 1;" ::: "memory");
        else                  asm volatile("cp.async.wait_group 0;" ::: "memory");
        __syncthreads();

        const uint32_t st   = sbase + (c2 % 3) * STAGE_BYTES;
        const uint32_t aHiB = st;
        const uint32_t aLoB = st + TILE_BYTES;
        const uint32_t bHiB = st + 2 * TILE_BYTES;
        const uint32_t bLoB = st + 3 * TILE_BYTES;

#pragma unroll
        for (int ks = 0; ks < 4; ks++) {
            uint32_t bh[4][2], bl[4][2];
            const int bk = ks * 16 + bK8 * 8;
#pragma unroll
            for (int nt = 0; nt < 4; nt++) {
                uint32_t off = (uint32_t)((bRow + nt * 8) * 128 + bk * 2);
                uint32_t sw = SWZ(off);
                ldmx2(bh[nt], bHiB + sw);
                ldmx2(bl[nt], bLoB + sw);
            }
            const int ak = ks * 16 + aK8 * 8;
#pragma unroll
            for (int mt = 0; mt < 4; mt++) {
                uint32_t off = (uint32_t)((aRow + mt * 16) * 128 + ak * 2);
                uint32_t sw = SWZ(off);
                uint32_t ah[4], al[4];
                ldmx4(ah, aHiB + sw);
                ldmx4(al, aLoB + sw);
#pragma unroll
                for (int nt = 0; nt < 4; nt++) {
                    mma16816(acc[mt][nt], ah, bh[nt]);
                    mma16816(acc[mt][nt], ah, bl[nt]);
                    mma16816(acc[mt][nt], al, bh[nt]);
                }
            }
        }
        __syncthreads();
        if (c2 + 3 < NC)
            load_stage_gemm(sbase + (c2 % 3) * STAGE_BYTES, tid, mBase, nBase,
                            (c2 + 3) * 64, Ahi, Alo, Bhi, Blo);
    }

    // epilogue: write acc to C
    const int colInTile0 = wn * 32 + (lane & 3) * 2;
    const int row0       = wm * 64 + (lane >> 2);
#pragma unroll
    for (int mt = 0; mt < 4; mt++) {
#pragma unroll
        for (int half = 0; half < 2; half++) {
            int grow = mBase + row0 + mt * 16 + half * 8;
#pragma unroll
            for (int nt = 0; nt < 4; nt++) {
                int lcol = colInTile0 + nt * 8;
                float2 v = make_float2(acc[mt][nt][half * 2],
                                       acc[mt][nt][half * 2 + 1]);
                if (CMODE) {
                    int b = grow >> 11, srow = grow & 2047;
                    int h = (nBase + lcol) >> 7;
                    int d = lcol & 127;
                    *reinterpret_cast<float2*>(
                        C + (((size_t)(b * nH + h)) * S_LEN + srow) * HDIM + d) = v;
                } else {
                    *reinterpret_cast<float2*>(C + (size_t)grow * N + nBase + lcol) = v;
                }
            }
        }
    }
}

// ============================== RoPE =======================================
__global__ void rope_kernel(float* __restrict__ X, int nH, float scale, int total)
{
    int idx = blockIdx.x * blockDim.x + threadIdx.x;
    if (idx >= total) return;
    int i  = idx & 63;
    int s  = (idx >> 6) & (S_LEN - 1);
    int bh = idx >> 17;
    size_t base = ((size_t)bh * S_LEN + s) * HDIM;
    float inv_freq = expf(-(float)i * (logf(10000.0f) / 64.0f));
    float ang = (float)s * inv_freq;
    float c = cosf(ang), sn = sinf(ang);
    float x1 = X[base + i];
    float x2 = X[base + i + 64];
    X[base + i]       = (x1 * c - x2 * sn) * scale;
    X[base + i + 64]  = (x2 * c + x1 * sn) * scale;
}

// ======================= flash attention (fp32) ============================
__global__ void __launch_bounds__(256, 1) attn_kernel()
{
    extern __shared__ float sm[];
    float* Qt   = sm;                    // 128*68
    float* Kt   = Qt + 128 * 68;         // 128*68
    float* Vs   = Kt + 128 * 68;         // 64*132
    float* Ps   = Vs + 64 * 132;         // 64*68
    float* f_sh = Ps + 64 * 68;          // 64
    float* l_sh = f_sh + 64;             // 64

    const int tid   = threadIdx.x;
    const int qtile = blockIdx.x;
    const int h     = blockIdx.y;
    const int b     = blockIdx.z;
    const int hk    = h >> 2;
    const int q0    = qtile * 64;

    const float* Qg = g_Q + (((size_t)(b * NHEADS + h)) * S_LEN + q0) * HDIM;
    const float* Kg = g_K + ((size_t)(b * NKV + hk)) * S_LEN * HDIM;
    const float* Vg = g_V + ((size_t)(b * NKV + hk)) * S_LEN * HDIM;

#pragma unroll
    for (int it = 0; it < 8; it++) {
        int slot = tid + it * 256;
        int r  = slot >> 5;
        int c4 = slot & 31;
        float4 v = *reinterpret_cast<const float4*>(Qg + (size_t)r * HDIM + c4 * 4);
        Qt[(c4 * 4 + 0) * 68 + r] = v.x;
        Qt[(c4 * 4 + 1) * 68 + r] = v.y;
        Qt[(c4 * 4 + 2) * 68 + r] = v.z;
        Qt[(c4 * 4 + 3) * 68 + r] = v.w;
    }

    const int tx = tid & 15;
    const int ty = tid >> 4;
    const int qy = ty * 4;
    const int kx = tx * 4;
    const int dx = tx * 8;

    float accO[4][8];
#pragma unroll
    for (int i = 0; i < 4; i++)
#pragma unroll
        for (int j = 0; j < 8; j++) accO[i][j] = 0.f;

    const int srow  = tid >> 2;
    const int spart = tid & 3;
    float m_run = -1e30f;
    float l_run = 0.f;

    int kt_lo = qtile - 8; if (kt_lo < 0) kt_lo = 0;

    for (int kt = kt_lo; kt <= qtile; kt++) {
        const int k0 = kt * 64;
#pragma unroll
        for (int it = 0; it < 8; it++) {
            int slot = tid + it * 256;
            int r  = slot >> 5;
            int c4 = slot & 31;
            float4 kv = *reinterpret_cast<const float4*>(Kg + (size_t)(k0 + r) * HDIM + c4 * 4);
            Kt[(c4 * 4 + 0) * 68 + r] = kv.x;
            Kt[(c4 * 4 + 1) * 68 + r] = kv.y;
            Kt[(c4 * 4 + 2) * 68 + r] = kv.z;
            Kt[(c4 * 4 + 3) * 68 + r] = kv.w;
            float4 vv = *reinterpret_cast<const float4*>(Vg + (size_t)(k0 + r) * HDIM + c4 * 4);
            *reinterpret_cast<float4*>(&Vs[r * 132 + c4 * 4]) = vv;
        }
        __syncthreads();

        float sc[4][4];
#pragma unroll
        for (int i = 0; i < 4; i++)
#pragma unroll
            for (int j = 0; j < 4; j++) sc[i][j] = 0.f;
#pragma unroll 4
        for (int d = 0; d < 128; d++) {
            float a[4], bb[4];
            *reinterpret_cast<float4*>(a)  = *reinterpret_cast<float4*>(&Qt[d * 68 + qy]);
            *reinterpret_cast<float4*>(bb) = *reinterpret_cast<float4*>(&Kt[d * 68 + kx]);
#pragma unroll
            for (int i = 0; i < 4; i++)
#pragma unroll
                for (int j = 0; j < 4; j++)
                    sc[i][j] = fmaf(a[i], bb[j], sc[i][j]);
        }
#pragma unroll
        for (int i = 0; i < 4; i++) {
            int gi = q0 + qy + i;
#pragma unroll
            for (int j = 0; j < 4; j++) {
                int gj = k0 + kx + j;
                bool ok = (gj <= gi) && (gi - gj <= WINDOW);
                Ps[(qy + i) * 68 + kx + j] = ok ? sc[i][j] : -1e30f;
            }
        }
        __syncthreads();

        float vals[16];
        float local_max = -1e30f;
#pragma unroll
        for (int u = 0; u < 16; u++) {
            vals[u] = Ps[srow * 68 + spart * 16 + u];
            local_max = fmaxf(local_max, vals[u]);
        }
        local_max = fmaxf(local_max, __shfl_xor_sync(0xffffffffu, local_max, 1));
        local_max = fmaxf(local_max, __shfl_xor_sync(0xffffffffu, local_max, 2));
        float m_new = fmaxf(m_run, local_max);
        float fac   = __expf(m_run - m_new);
        float psum  = 0.f;
#pragma unroll
        for (int u = 0; u < 16; u++) {
            float p = (vals[u] > -1e29f) ? __expf(vals[u] - m_new) : 0.f;
            Ps[srow * 68 + spart * 16 + u] = p;
            psum += p;
        }
        psum += __shfl_xor_sync(0xffffffffu, psum, 1);
        psum += __shfl_xor_sync(0xffffffffu, psum, 2);
        l_run = l_run * fac + psum;
        m_run = m_new;
        if (spart == 0) f_sh[srow] = fac;
        __syncthreads();

#pragma unroll
        for (int i = 0; i < 4; i++) {
            float f = f_sh[qy + i];
#pragma unroll
            for (int j = 0; j < 8; j++) accO[i][j] *= f;
        }
#pragma unroll 2
        for (int kk = 0; kk < 64; kk++) {
            float v[8];
            *reinterpret_cast<float4*>(v)     = *reinterpret_cast<float4*>(&Vs[kk * 132 + dx]);
            *reinterpret_cast<float4*>(v + 4) = *reinterpret_cast<float4*>(&Vs[kk * 132 + dx + 4]);
#pragma unroll
            for (int i = 0; i < 4; i++) {
                float p = Ps[(qy + i) * 68 + kk];
#pragma unroll
                for (int j = 0; j < 8; j++)
                    accO[i][j] = fmaf(p, v[j], accO[i][j]);
            }
        }
        __syncthreads();
    }

    if (spart == 0) l_sh[srow] = l_run;
    __syncthreads();

    float* Og = g_O + (((size_t)(b * NHEADS + h)) * S_LEN + q0) * HDIM;
#pragma unroll
    for (int i = 0; i < 4; i++) {
        float inv_l = 1.0f / l_sh[qy + i];
        float4 o0 = make_float4(accO[i][0] * inv_l, accO[i][1] * inv_l,
                                accO[i][2] * inv_l, accO[i][3] * inv_l);
        float4 o1 = make_float4(accO[i][4] * inv_l, accO[i][5] * inv_l,
                                accO[i][6] * inv_l, accO[i][7] * inv_l);
        *reinterpret_cast<float4*>(Og + (size_t)(qy + i) * HDIM + dx)     = o0;
        *reinterpret_cast<float4*>(Og + (size_t)(qy + i) * HDIM + dx + 4) = o1;
    }
}

// ---------------------------------------------------------------------------
extern "C" void kernel_launch(void* const* d_in, const int* in_sizes, int n_in,
                              void* d_out, int out_size)
{
    (void)in_sizes; (void)n_in; (void)out_size;
    const float* hidden = (const float*)d_in[0];
    const float* Wq     = (const float*)d_in[1];
    const float* Wk     = (const float*)d_in[2];
    const float* Wv     = (const float*)d_in[3];
    const float* Wo     = (const float*)d_in[4];
    float* out          = (float*)d_out;

    float* q; cudaGetSymbolAddress((void**)&q, g_Q);
    float* k; cudaGetSymbolAddress((void**)&k, g_K);
    float* v; cudaGetSymbolAddress((void**)&v, g_V);
    float* o; cudaGetSymbolAddress((void**)&o, g_O);
    __nv_bfloat16 *xhi, *xlo, *wqh, *wql, *wkh, *wkl, *wvh, *wvl, *woh, *wol, *ohi, *olo;
    cudaGetSymbolAddress((void**)&xhi, g_Xhi);  cudaGetSymbolAddress((void**)&xlo, g_Xlo);
    cudaGetSymbolAddress((void**)&wqh, g_WqThi); cudaGetSymbolAddress((void**)&wql, g_WqTlo);
    cudaGetSymbolAddress((void**)&wkh, g_WkThi); cudaGetSymbolAddress((void**)&wkl, g_WkTlo);
    cudaGetSymbolAddress((void**)&wvh, g_WvThi); cudaGetSymbolAddress((void**)&wvl, g_WvTlo);
    cudaGetSymbolAddress((void**)&woh, g_WoThi); cudaGetSymbolAddress((void**)&wol, g_WoTlo);
    cudaGetSymbolAddress((void**)&ohi, g_Ohi);   cudaGetSymbolAddress((void**)&olo, g_Olo);

    // ---- split / transpose preprocessing ----
    {
        int n4 = (M_ROWS * HID) / 4;
        split_rowmajor_kernel<<<(n4 + 255) / 256, 256>>>(hidden, xhi, xlo, n4);
        dim3 gq(HID / 32, HID / 32);
        transpose_split_kernel<<<gq, 256>>>(Wq, wqh, wql, HID, HID);
        dim3 gkv(KVDIM / 32, HID / 32);
        transpose_split_kernel<<<gkv, 256>>>(Wk, wkh, wkl, HID, KVDIM);
        transpose_split_kernel<<<gkv, 256>>>(Wv, wvh, wvl, HID, KVDIM);
        transpose_split_kernel<<<gq, 256>>>(Wo, woh, wol, HID, HID);
    }

    // ---- QKV projections on tensor cores (mma.sync) ----
    cudaFuncSetAttribute(mma_gemm_kernel,
                         cudaFuncAttributeMaxDynamicSharedMemorySize, GEMM_SMEM);
    {
        dim3 gqk(HID / 128, M_ROWS / 128);
        mma_gemm_kernel<<<gqk, 256, GEMM_SMEM>>>(xhi, xlo, wqh, wql, q, HID, NHEADS, 1);
        dim3 gkv(KVDIM / 128, M_ROWS / 128);
        mma_gemm_kernel<<<gkv, 256, GEMM_SMEM>>>(xhi, xlo, wkh, wkl, k, KVDIM, NKV, 1);
        mma_gemm_kernel<<<gkv, 256, GEMM_SMEM>>>(xhi, xlo, wvh, wvl, v, KVDIM, NKV, 1);
    }

    // ---- RoPE ----
    {
        int totQ = BATCH * NHEADS * S_LEN * 64;
        int totK = BATCH * NKV * S_LEN * 64;
        float qscale = 1.0f / sqrtf((float)HDIM);
        rope_kernel<<<(totQ + 255) / 256, 256>>>(q, NHEADS, qscale, totQ);
        rope_kernel<<<(totK + 255) / 256, 256>>>(k, NKV, 1.0f, totK);
    }

    // ---- attention ----
    {
        size_t smem = (size_t)(128 * 68 * 2 + 64 * 132 + 64 * 68 + 128) * sizeof(float);
        cudaFuncSetAttribute(attn_kernel,
                             cudaFuncAttributeMaxDynamicSharedMemorySize, (int)smem);
        dim3 g(S_LEN / 64, NHEADS, BATCH);
        attn_kernel<<<g, 256, smem>>>();
    }

    // ---- output projection ----
    {
        int n4 = (M_ROWS * HID) / 4;
        splitO_kernel<<<(n4 + 255) / 256, 256>>>(o, ohi, olo, n4);
        dim3 go(HID / 128, M_ROWS / 128);
        mma_gemm_kernel<<<go, 256, GEMM_SMEM>>>(ohi, olo, woh, wol, out, HID, NHEADS, 0);
    }
}

// round 4
// speedup vs baseline: 3.3783x; 2.1848x over previous
#include <cuda_runtime.h>
#include <cuda_bf16.h>
#include <math.h>
#include <stdint.h>

#define S_LEN   2048
#define BATCH   2
#define NHEADS  32
#define NKV     8
#define HDIM    128
#define HID     4096
#define KVDIM   1024
#define M_ROWS  4096   // B*S
#define WINDOW  512    // SLIDING_WINDOW // 2
#define GK      4096   // GEMM K
#define NC      (GK/64)

// ======================== scratch buffers ==================================
__device__ float g_Q[(size_t)BATCH * NHEADS * S_LEN * HDIM];
__device__ float g_K[(size_t)BATCH * NKV   * S_LEN * HDIM];
__device__ float g_V[(size_t)BATCH * NKV   * S_LEN * HDIM];
__device__ float g_O[(size_t)BATCH * NHEADS * S_LEN * HDIM];

__device__ __nv_bfloat16 g_Xhi[(size_t)M_ROWS * HID];
__device__ __nv_bfloat16 g_Xlo[(size_t)M_ROWS * HID];
__device__ __nv_bfloat16 g_WqThi[(size_t)HID * HID];
__device__ __nv_bfloat16 g_WqTlo[(size_t)HID * HID];
__device__ __nv_bfloat16 g_WkThi[(size_t)KVDIM * HID];
__device__ __nv_bfloat16 g_WkTlo[(size_t)KVDIM * HID];
__device__ __nv_bfloat16 g_WvThi[(size_t)KVDIM * HID];
__device__ __nv_bfloat16 g_WvTlo[(size_t)KVDIM * HID];
__device__ __nv_bfloat16 g_WoThi[(size_t)HID * HID];
__device__ __nv_bfloat16 g_WoTlo[(size_t)HID * HID];
__device__ __nv_bfloat16 g_Ohi[(size_t)M_ROWS * HID];
__device__ __nv_bfloat16 g_Olo[(size_t)M_ROWS * HID];

// bf16 attention operands
__device__ __nv_bfloat16 g_Qbh[(size_t)BATCH * NHEADS * S_LEN * HDIM];
__device__ __nv_bfloat16 g_Qbl[(size_t)BATCH * NHEADS * S_LEN * HDIM];
__device__ __nv_bfloat16 g_Kbh[(size_t)BATCH * NKV * S_LEN * HDIM];
__device__ __nv_bfloat16 g_Kbl[(size_t)BATCH * NKV * S_LEN * HDIM];
__device__ __nv_bfloat16 g_Vth[(size_t)BATCH * NKV * HDIM * S_LEN];  // [b,hk,d,s]
__device__ __nv_bfloat16 g_Vtl[(size_t)BATCH * NKV * HDIM * S_LEN];

// ======================= low-level helpers =================================
__device__ __forceinline__ uint32_t smem_u32(const void* p) {
    uint32_t a;
    asm("{ .reg .u64 t; cvta.to.shared.u64 t, %1; cvt.u32.u64 %0, t; }"
        : "=r"(a) : "l"(p));
    return a;
}
__device__ __forceinline__ void cpasync16(uint32_t saddr, const void* g) {
    asm volatile("cp.async.cg.shared.global [%0], [%1], 16;"
                 :: "r"(saddr), "l"(g) : "memory");
}
#define SWZ(o) ((o) ^ (((o) >> 3) & 0x70))

__device__ __forceinline__ void ldmx4(uint32_t* r, uint32_t addr) {
    asm volatile("ldmatrix.sync.aligned.m8n8.x4.shared.b16 {%0,%1,%2,%3}, [%4];"
                 : "=r"(r[0]), "=r"(r[1]), "=r"(r[2]), "=r"(r[3]) : "r"(addr));
}
__device__ __forceinline__ void ldmx2(uint32_t* r, uint32_t addr) {
    asm volatile("ldmatrix.sync.aligned.m8n8.x2.shared.b16 {%0,%1}, [%2];"
                 : "=r"(r[0]), "=r"(r[1]) : "r"(addr));
}
__device__ __forceinline__ void mma16816(float* d, const uint32_t* a, const uint32_t* b) {
    asm volatile("mma.sync.aligned.m16n8k16.row.col.f32.bf16.bf16.f32 "
                 "{%0,%1,%2,%3}, {%4,%5,%6,%7}, {%8,%9}, {%0,%1,%2,%3};"
                 : "+f"(d[0]), "+f"(d[1]), "+f"(d[2]), "+f"(d[3])
                 : "r"(a[0]), "r"(a[1]), "r"(a[2]), "r"(a[3]),
                   "r"(b[0]), "r"(b[1]));
}

// fast exp for x <= ~0 (FMA-pipe; avoids MUFU throughput wall)
__device__ __forceinline__ float fast_exp(float x) {
    float y = x * 1.4426950408889634f;
    float r = rintf(y);
    float f = y - r;
    float p = 1.3697664e-3f;
    p = fmaf(p, f, 9.6784195e-3f);
    p = fmaf(p, f, 5.5503454e-2f);
    p = fmaf(p, f, 2.4022652e-1f);
    p = fmaf(p, f, 6.9314718e-1f);
    p = fmaf(p, f, 1.0f);
    int ri = (int)r;
    ri = ri < -126 ? -126 : (ri > 126 ? 126 : ri);
    float s = __int_as_float((uint32_t)(ri + 127) << 23);
    return p * s;
}

__device__ __forceinline__ void split1(float f, __nv_bfloat16& h, __nv_bfloat16& l) {
    h = __float2bfloat16_rn(f);
    l = __float2bfloat16_rn(f - __bfloat162float(h));
}
__device__ __forceinline__ uint32_t packbf(float a, float b) {
    __nv_bfloat162 t = __halves2bfloat162(__float2bfloat16_rn(a), __float2bfloat16_rn(b));
    return *reinterpret_cast<uint32_t*>(&t);
}

// ===================== split / transpose preprocessing =====================
__global__ void split_rowmajor_kernel(const float* __restrict__ X,
                                      __nv_bfloat16* __restrict__ hi,
                                      __nv_bfloat16* __restrict__ lo, int n4)
{
    int i = blockIdx.x * blockDim.x + threadIdx.x;
    if (i >= n4) return;
    float4 v = reinterpret_cast<const float4*>(X)[i];
    __nv_bfloat16 h0, h1, h2, h3, l0, l1, l2, l3;
    split1(v.x, h0, l0); split1(v.y, h1, l1);
    split1(v.z, h2, l2); split1(v.w, h3, l3);
    __nv_bfloat162* hp = reinterpret_cast<__nv_bfloat162*>(hi) + 2 * i;
    __nv_bfloat162* lp = reinterpret_cast<__nv_bfloat162*>(lo) + 2 * i;
    hp[0] = __halves2bfloat162(h0, h1); hp[1] = __halves2bfloat162(h2, h3);
    lp[0] = __halves2bfloat162(l0, l1); lp[1] = __halves2bfloat162(l2, l3);
}

__global__ void transpose_split_kernel(const float* __restrict__ W,
                                       __nv_bfloat16* __restrict__ hi,
                                       __nv_bfloat16* __restrict__ lo,
                                       int K, int N)
{
    __shared__ float t[32][33];
    int k0 = blockIdx.y * 32, n0 = blockIdx.x * 32;
    int c = threadIdx.x & 31, r = threadIdx.x >> 5;
#pragma unroll
    for (int p = 0; p < 32; p += 8)
        t[r + p][c] = W[(size_t)(k0 + r + p) * N + n0 + c];
    __syncthreads();
#pragma unroll
    for (int p = 0; p < 32; p += 8) {
        float f = t[c][r + p];
        __nv_bfloat16 h, l;
        split1(f, h, l);
        size_t o = (size_t)(n0 + r + p) * K + k0 + c;
        hi[o] = h; lo[o] = l;
    }
}

__global__ void splitO_kernel(const float* __restrict__ O,
                              __nv_bfloat16* __restrict__ hi,
                              __nv_bfloat16* __restrict__ lo, int n4)
{
    int i = blockIdx.x * blockDim.x + threadIdx.x;
    if (i >= n4) return;
    int e = i * 4;
    int m = e >> 12, col = e & 4095;
    int h = col >> 7, d = col & 127;
    int b = m >> 11, s = m & 2047;
    float4 v = *reinterpret_cast<const float4*>(
        O + ((((size_t)(b * NHEADS + h)) * S_LEN + s) * HDIM + d));
    __nv_bfloat16 h0, h1, h2, h3, l0, l1, l2, l3;
    split1(v.x, h0, l0); split1(v.y, h1, l1);
    split1(v.z, h2, l2); split1(v.w, h3, l3);
    __nv_bfloat162* hp = reinterpret_cast<__nv_bfloat162*>(hi) + 2 * i;
    __nv_bfloat162* lp = reinterpret_cast<__nv_bfloat162*>(lo) + 2 * i;
    hp[0] = __halves2bfloat162(h0, h1); hp[1] = __halves2bfloat162(h2, h3);
    lp[0] = __halves2bfloat162(l0, l1); lp[1] = __halves2bfloat162(l2, l3);
}

// RoPE fp32 -> bf16 hi/lo (same [*,s,d] layout); folds `scale` in
__global__ void rope_split_kernel(const float* __restrict__ X,
                                  __nv_bfloat16* __restrict__ Xh,
                                  __nv_bfloat16* __restrict__ Xl,
                                  float scale, int total)
{
    int idx = blockIdx.x * blockDim.x + threadIdx.x;
    if (idx >= total) return;
    int i  = idx & 63;
    int s  = (idx >> 6) & (S_LEN - 1);
    int bh = idx >> 17;
    size_t base = ((size_t)bh * S_LEN + s) * HDIM;
    float inv_freq = expf(-(float)i * (logf(10000.0f) / 64.0f));
    float ang = (float)s * inv_freq;
    float c = cosf(ang), sn = sinf(ang);
    float x1 = X[base + i];
    float x2 = X[base + i + 64];
    float y1 = (x1 * c - x2 * sn) * scale;
    float y2 = (x2 * c + x1 * sn) * scale;
    __nv_bfloat16 h, l;
    split1(y1, h, l); Xh[base + i] = h;      Xl[base + i] = l;
    split1(y2, h, l); Xh[base + i + 64] = h; Xl[base + i + 64] = l;
}

// g_V [b,hk,s,d] fp32 -> Vt hi/lo [b,hk,d,s] bf16
__global__ void transposeV_split_kernel(const float* __restrict__ V,
                                        __nv_bfloat16* __restrict__ Vth,
                                        __nv_bfloat16* __restrict__ Vtl)
{
    __shared__ float t[32][33];
    int bhk = blockIdx.z;
    int s0 = blockIdx.x * 32, d0 = blockIdx.y * 32;
    const float* src = V + (size_t)bhk * S_LEN * HDIM;
    int c = threadIdx.x & 31, r = threadIdx.x >> 5;
#pragma unroll
    for (int p = 0; p < 32; p += 8)
        t[r + p][c] = src[(size_t)(s0 + r + p) * HDIM + d0 + c];
    __syncthreads();
    size_t dstbase = (size_t)bhk * HDIM * S_LEN;
#pragma unroll
    for (int p = 0; p < 32; p += 8) {
        float f = t[c][r + p];              // = V[s0+c][d0+r+p]
        __nv_bfloat16 h, l;
        split1(f, h, l);
        size_t o = dstbase + (size_t)(d0 + r + p) * S_LEN + s0 + c;
        Vth[o] = h; Vtl[o] = l;
    }
}

// =================== mma.sync bf16-split GEMM (unchanged) ==================
#define TILE_BYTES  16384
#define STAGE_BYTES (4 * TILE_BYTES)
#define GEMM_SMEM   (3 * STAGE_BYTES)

__device__ __forceinline__ void load_stage_gemm(
    uint32_t stage_base, int tid, int mBase, int nBase, int kb,
    const __nv_bfloat16* __restrict__ Ahi, const __nv_bfloat16* __restrict__ Alo,
    const __nv_bfloat16* __restrict__ Bhi, const __nv_bfloat16* __restrict__ Blo)
{
#pragma unroll
    for (int u = 0; u < 4; ++u) {
        int unit = tid + u * 256;
        int r = unit >> 3, c16 = unit & 7;
        uint32_t soff = (uint32_t)(r * 128 + c16 * 16);
        uint32_t sw = SWZ(soff);
        size_t ga = (size_t)(mBase + r) * GK + kb + c16 * 8;
        size_t gb = (size_t)(nBase + r) * GK + kb + c16 * 8;
        cpasync16(stage_base + sw,                  Ahi + ga);
        cpasync16(stage_base + TILE_BYTES + sw,     Alo + ga);
        cpasync16(stage_base + 2 * TILE_BYTES + sw, Bhi + gb);
        cpasync16(stage_base + 3 * TILE_BYTES + sw, Blo + gb);
    }
    asm volatile("cp.async.commit_group;" ::: "memory");
}

__global__ void __launch_bounds__(256, 1) mma_gemm_kernel(
    const __nv_bfloat16* __restrict__ Ahi, const __nv_bfloat16* __restrict__ Alo,
    const __nv_bfloat16* __restrict__ Bhi, const __nv_bfloat16* __restrict__ Blo,
    float* __restrict__ C, int N, int nH, int CMODE)
{
    extern __shared__ __align__(1024) char smem_raw[];
    const uint32_t sbase = smem_u32(smem_raw);
    const int tid  = threadIdx.x;
    const int wid  = tid >> 5, lane = tid & 31;
    const int wm   = wid >> 2;
    const int wn   = wid & 3;
    const int mBase = blockIdx.y * 128;
    const int nBase = blockIdx.x * 128;

    float acc[4][4][4];
#pragma unroll
    for (int mt = 0; mt < 4; mt++)
#pragma unroll
        for (int nt = 0; nt < 4; nt++)
#pragma unroll
            for (int e = 0; e < 4; e++) acc[mt][nt][e] = 0.f;

    load_stage_gemm(sbase + 0 * STAGE_BYTES, tid, mBase, nBase, 0,   Ahi, Alo, Bhi, Blo);
    load_stage_gemm(sbase + 1 * STAGE_BYTES, tid, mBase, nBase, 64,  Ahi, Alo, Bhi, Blo);
    load_stage_gemm(sbase + 2 * STAGE_BYTES, tid, mBase, nBase, 128, Ahi, Alo, Bhi, Blo);

    const int aRow = wm * 64 + (lane & 15);
    const int aK8  = (lane >> 4);
    const int bRow = wn * 32 + (lane & 7);
    const int bK8  = ((lane >> 3) & 1);

    for (int c2 = 0; c2 < NC; ++c2) {
        if (c2 + 2 < NC)      asm volatile("cp.async.wait_group 2;" ::: "memory");
        else if (c2 + 1 < NC) asm volatile("cp.async.wait_group 1;" ::: "memory");
        else                  asm volatile("cp.async.wait_group 0;" ::: "memory");
        __syncthreads();

        const uint32_t st   = sbase + (c2 % 3) * STAGE_BYTES;
        const uint32_t aHiB = st;
        const uint32_t aLoB = st + TILE_BYTES;
        const uint32_t bHiB = st + 2 * TILE_BYTES;
        const uint32_t bLoB = st + 3 * TILE_BYTES;

#pragma unroll
        for (int ks = 0; ks < 4; ks++) {
            uint32_t bh[4][2], bl[4][2];
            const int bk = ks * 16 + bK8 * 8;
#pragma unroll
            for (int nt = 0; nt < 4; nt++) {
                uint32_t off = (uint32_t)((bRow + nt * 8) * 128 + bk * 2);
                uint32_t sw = SWZ(off);
                ldmx2(bh[nt], bHiB + sw);
                ldmx2(bl[nt], bLoB + sw);
            }
            const int ak = ks * 16 + aK8 * 8;
#pragma unroll
            for (int mt = 0; mt < 4; mt++) {
                uint32_t off = (uint32_t)((aRow + mt * 16) * 128 + ak * 2);
                uint32_t sw = SWZ(off);
                uint32_t ah[4], al[4];
                ldmx4(ah, aHiB + sw);
                ldmx4(al, aLoB + sw);
#pragma unroll
                for (int nt = 0; nt < 4; nt++) {
                    mma16816(acc[mt][nt], ah, bh[nt]);
                    mma16816(acc[mt][nt], ah, bl[nt]);
                    mma16816(acc[mt][nt], al, bh[nt]);
                }
            }
        }
        __syncthreads();
        if (c2 + 3 < NC)
            load_stage_gemm(sbase + (c2 % 3) * STAGE_BYTES, tid, mBase, nBase,
                            (c2 + 3) * 64, Ahi, Alo, Bhi, Blo);
    }

    const int colInTile0 = wn * 32 + (lane & 3) * 2;
    const int row0       = wm * 64 + (lane >> 2);
#pragma unroll
    for (int mt = 0; mt < 4; mt++) {
#pragma unroll
        for (int half = 0; half < 2; half++) {
            int grow = mBase + row0 + mt * 16 + half * 8;
#pragma unroll
            for (int nt = 0; nt < 4; nt++) {
                int lcol = colInTile0 + nt * 8;
                float2 v = make_float2(acc[mt][nt][half * 2],
                                       acc[mt][nt][half * 2 + 1]);
                if (CMODE) {
                    int b = grow >> 11, srow = grow & 2047;
                    int h = (nBase + lcol) >> 7;
                    int d = lcol & 127;
                    *reinterpret_cast<float2*>(
                        C + (((size_t)(b * nH + h)) * S_LEN + srow) * HDIM + d) = v;
                } else {
                    *reinterpret_cast<float2*>(C + (size_t)grow * N + nBase + lcol) = v;
                }
            }
        }
    }
}

// ================= tensor-core flash attention (bf16 hi/lo) ================
// CTA: 128 q rows x (64-key tiles), 8 warps (m16 each, full n=64).
// smem: 2 stages x 64KB: [Khi 16K][Klo 16K][Vthi 16K][Vtlo 16K]
// K tile smem row = sub*64 + key (sub = d/64), 128B rows, SW128.
// Vt tile smem row = d (0..127), cols = 64 keys, 128B rows.
#define AT_STAGE 65536
#define ATTN_SMEM (2 * AT_STAGE)

__global__ void __launch_bounds__(256, 1) attn_mma_kernel()
{
    extern __shared__ __align__(1024) char smem_raw[];
    const uint32_t sb = smem_u32(smem_raw);
    const int tid = threadIdx.x, wid = tid >> 5, lane = tid & 31;
    const int qt = blockIdx.x, h = blockIdx.y, b = blockIdx.z;
    const int hk = h >> 2;
    const int q0 = qt * 128;
    const int bh = b * NHEADS + h, bhk = b * NKV + hk;

    const __nv_bfloat16* Qhg = g_Qbh + ((size_t)bh * S_LEN + q0) * HDIM;
    const __nv_bfloat16* Qlg = g_Qbl + ((size_t)bh * S_LEN + q0) * HDIM;
    const __nv_bfloat16* Khg = g_Kbh + (size_t)bhk * S_LEN * HDIM;
    const __nv_bfloat16* Klg = g_Kbl + (size_t)bhk * S_LEN * HDIM;
    const __nv_bfloat16* Vhg = g_Vth + (size_t)bhk * HDIM * S_LEN;
    const __nv_bfloat16* Vlg = g_Vtl + (size_t)bhk * HDIM * S_LEN;

    // ---- stage Q (hi at sb+0, lo at sb+32768; 2 subs of 16KB each) ----
#pragma unroll
    for (int it = 0; it < 16; it++) {
        int u = tid + it * 256;               // 0..4095
        int bf = u >> 11;
        int w  = u & 2047;
        int r = w >> 4, c16 = w & 15;
        int sub = c16 >> 3;
        uint32_t off = (uint32_t)(bf * 32768 + sub * 16384 + r * 128 + (c16 & 7) * 16);
        const __nv_bfloat16* g = (bf ? Qlg : Qhg) + (size_t)r * HDIM + c16 * 8;
        cpasync16(sb + SWZ(off), g);
    }
    asm volatile("cp.async.commit_group;" ::: "memory");
    asm volatile("cp.async.wait_group 0;" ::: "memory");
    __syncthreads();

    uint32_t qh[8][4], ql[8][4];
    {
        int row = wid * 16 + (lane & 15);
        int k8 = lane >> 4;
#pragma unroll
        for (int kf = 0; kf < 8; kf++) {
            int sub = kf >> 2;
            uint32_t off = (uint32_t)(sub * 16384 + row * 128 + ((kf & 3) * 16 + k8 * 8) * 2);
            uint32_t sw = SWZ(off);
            ldmx4(qh[kf], sb + sw);
            ldmx4(ql[kf], sb + 32768 + sw);
        }
    }
    __syncthreads();

    float o[16][4];
#pragma unroll
    for (int nf = 0; nf < 16; nf++)
#pragma unroll
        for (int e = 0; e < 4; e++) o[nf][e] = 0.f;

    float m0 = -1e30f, m1 = -1e30f, l0 = 0.f, l1 = 0.f;
    const int g0row = q0 + wid * 16 + (lane >> 2);

    int kt_lo = 2 * qt - 8; if (kt_lo < 0) kt_lo = 0;
    const int nt = 2 * qt + 1 - kt_lo + 1;

    // stage loader
    auto load_kv = [&](int stage, int kt) {
        const int k0 = kt * 64;
        const uint32_t stb = sb + (uint32_t)stage * AT_STAGE;
#pragma unroll
        for (int it = 0; it < 16; it++) {
            int u = tid + it * 256;           // 0..4095
            int buf = u >> 10;
            int w = u & 1023;
            int r = w >> 3, c16 = w & 7;
            uint32_t off = (uint32_t)(buf * 16384 + r * 128 + c16 * 16);
            const __nv_bfloat16* g;
            if (buf < 2) {
                int key = r & 63, sub = r >> 6;
                g = (buf ? Klg : Khg) + (size_t)(k0 + key) * HDIM + sub * 64 + c16 * 8;
            } else {
                g = (buf == 3 ? Vlg : Vhg) + (size_t)r * S_LEN + k0 + c16 * 8;
            }
            cpasync16(stb + SWZ(off), g);
        }
        asm volatile("cp.async.commit_group;" ::: "memory");
    };

    load_kv(0, kt_lo);
    load_kv(1, kt_lo + 1);

    for (int i = 0; i < nt; i++) {
        const int kt = kt_lo + i;
        const int k0 = kt * 64;
        if (i + 1 < nt) asm volatile("cp.async.wait_group 1;" ::: "memory");
        else            asm volatile("cp.async.wait_group 0;" ::: "memory");
        __syncthreads();
        const uint32_t stb = sb + (uint32_t)(i & 1) * AT_STAGE;

        // ---- S = Q K^T (3-pass) ----
        float s[8][4];
#pragma unroll
        for (int nf = 0; nf < 8; nf++)
#pragma unroll
            for (int e = 0; e < 4; e++) s[nf][e] = 0.f;

#pragma unroll
        for (int kf = 0; kf < 8; kf++) {
            const int sub = kf >> 2;
            const int klocal = (kf & 3) * 16;
            uint32_t kbh[8][2], kbl[8][2];
#pragma unroll
            for (int np = 0; np < 4; np++) {
                int m = lane >> 3;
                int nf2 = np * 2 + (m >> 1);
                int key = nf2 * 8 + (lane & 7);
                int dl = klocal + (m & 1) * 8;
                uint32_t off = (uint32_t)((sub * 64 + key) * 128 + dl * 2);
                uint32_t sw = SWZ(off);
                uint32_t r4[4];
                ldmx4(r4, stb + sw);
                kbh[np * 2][0] = r4[0]; kbh[np * 2][1] = r4[1];
                kbh[np * 2 + 1][0] = r4[2]; kbh[np * 2 + 1][1] = r4[3];
                ldmx4(r4, stb + 16384 + sw);
                kbl[np * 2][0] = r4[0]; kbl[np * 2][1] = r4[1];
                kbl[np * 2 + 1][0] = r4[2]; kbl[np * 2 + 1][1] = r4[3];
            }
#pragma unroll
            for (int nf = 0; nf < 8; nf++) {
                mma16816(s[nf], qh[kf], kbh[nf]);
                mma16816(s[nf], qh[kf], kbl[nf]);
                mma16816(s[nf], ql[kf], kbh[nf]);
            }
        }

        // ---- mask (boundary tiles only) ----
        if ((k0 + 63 > q0) || (q0 + 127 - k0 > WINDOW)) {
#pragma unroll
            for (int nf = 0; nf < 8; nf++)
#pragma unroll
                for (int e = 0; e < 4; e++) {
                    int row = g0row + ((e >= 2) ? 8 : 0);
                    int col = k0 + nf * 8 + (lane & 3) * 2 + (e & 1);
                    if (col > row || row - col > WINDOW) s[nf][e] = -1e30f;
                }
        }

        // ---- streaming softmax (in-warp) ----
        float mx0 = -1e30f, mx1 = -1e30f;
#pragma unroll
        for (int nf = 0; nf < 8; nf++) {
            mx0 = fmaxf(mx0, fmaxf(s[nf][0], s[nf][1]));
            mx1 = fmaxf(mx1, fmaxf(s[nf][2], s[nf][3]));
        }
        mx0 = fmaxf(mx0, __shfl_xor_sync(0xffffffffu, mx0, 1));
        mx0 = fmaxf(mx0, __shfl_xor_sync(0xffffffffu, mx0, 2));
        mx1 = fmaxf(mx1, __shfl_xor_sync(0xffffffffu, mx1, 1));
        mx1 = fmaxf(mx1, __shfl_xor_sync(0xffffffffu, mx1, 2));
        float mn0 = fmaxf(m0, mx0), mn1 = fmaxf(m1, mx1);
        float fac0 = fast_exp(m0 - mn0), fac1 = fast_exp(m1 - mn1);
        m0 = mn0; m1 = mn1;

        uint32_t ph[8][2], pl[8][2];
        float ps0 = 0.f, ps1 = 0.f;
#pragma unroll
        for (int nf = 0; nf < 8; nf++) {
            float p0 = fast_exp(s[nf][0] - mn0);
            float p1 = fast_exp(s[nf][1] - mn0);
            float p2 = fast_exp(s[nf][2] - mn1);
            float p3 = fast_exp(s[nf][3] - mn1);
            ps0 += p0 + p1; ps1 += p2 + p3;
            __nv_bfloat16 h0, lo0, h1, lo1, h2, lo2, h3, lo3;
            split1(p0, h0, lo0); split1(p1, h1, lo1);
            split1(p2, h2, lo2); split1(p3, h3, lo3);
            __nv_bfloat162 t;
            t = __halves2bfloat162(h0, h1);  ph[nf][0] = *reinterpret_cast<uint32_t*>(&t);
            t = __halves2bfloat162(h2, h3);  ph[nf][1] = *reinterpret_cast<uint32_t*>(&t);
            t = __halves2bfloat162(lo0, lo1); pl[nf][0] = *reinterpret_cast<uint32_t*>(&t);
            t = __halves2bfloat162(lo2, lo3); pl[nf][1] = *reinterpret_cast<uint32_t*>(&t);
        }
        ps0 += __shfl_xor_sync(0xffffffffu, ps0, 1);
        ps0 += __shfl_xor_sync(0xffffffffu, ps0, 2);
        ps1 += __shfl_xor_sync(0xffffffffu, ps1, 1);
        ps1 += __shfl_xor_sync(0xffffffffu, ps1, 2);
        l0 = l0 * fac0 + ps0;
        l1 = l1 * fac1 + ps1;

#pragma unroll
        for (int nf = 0; nf < 16; nf++) {
            o[nf][0] *= fac0; o[nf][1] *= fac0;
            o[nf][2] *= fac1; o[nf][3] *= fac1;
        }

        // ---- O += P @ Vt (3-pass) ----
#pragma unroll
        for (int kf2 = 0; kf2 < 4; kf2++) {
            uint32_t pah[4] = { ph[2 * kf2][0], ph[2 * kf2][1],
                                ph[2 * kf2 + 1][0], ph[2 * kf2 + 1][1] };
            uint32_t pal[4] = { pl[2 * kf2][0], pl[2 * kf2][1],
                                pl[2 * kf2 + 1][0], pl[2 * kf2 + 1][1] };
#pragma unroll
            for (int np = 0; np < 8; np++) {
                int m = lane >> 3;
                int drow = (np * 2 + (m >> 1)) * 8 + (lane & 7);
                int kl = kf2 * 16 + (m & 1) * 8;
                uint32_t off = (uint32_t)(32768 + drow * 128 + kl * 2);
                uint32_t sw = SWZ(off);
                uint32_t r4[4], r4l[4];
                ldmx4(r4,  stb + sw);
                ldmx4(r4l, stb + 16384 + sw);
                uint32_t vb0[2] = { r4[0], r4[1] },  vb1[2] = { r4[2], r4[3] };
                uint32_t vl0[2] = { r4l[0], r4l[1] }, vl1[2] = { r4l[2], r4l[3] };
                mma16816(o[np * 2],     pah, vb0);
                mma16816(o[np * 2],     pah, vl0);
                mma16816(o[np * 2],     pal, vb0);
                mma16816(o[np * 2 + 1], pah, vb1);
                mma16816(o[np * 2 + 1], pah, vl1);
                mma16816(o[np * 2 + 1], pal, vb1);
            }
        }
        __syncthreads();
        if (i + 2 < nt) load_kv(i & 1, kt + 2);
    }

    // ---- write O ----
    const float inv0 = 1.f / l0, inv1 = 1.f / l1;
    float* Og = g_O + ((size_t)bh * S_LEN + q0) * HDIM;
    const int r0 = wid * 16 + (lane >> 2);
    const int c0 = (lane & 3) * 2;
#pragma unroll
    for (int nf = 0; nf < 16; nf++) {
        int d = nf * 8 + c0;
        *reinterpret_cast<float2*>(Og + (size_t)r0 * HDIM + d) =
            make_float2(o[nf][0] * inv0, o[nf][1] * inv0);
        *reinterpret_cast<float2*>(Og + (size_t)(r0 + 8) * HDIM + d) =
            make_float2(o[nf][2] * inv1, o[nf][3] * inv1);
    }
}

// ---------------------------------------------------------------------------
extern "C" void kernel_launch(void* const* d_in, const int* in_sizes, int n_in,
                              void* d_out, int out_size)
{
    (void)in_sizes; (void)n_in; (void)out_size;
    const float* hidden = (const float*)d_in[0];
    const float* Wq     = (const float*)d_in[1];
    const float* Wk     = (const float*)d_in[2];
    const float* Wv     = (const float*)d_in[3];
    const float* Wo     = (const float*)d_in[4];
    float* out          = (float*)d_out;

    float* q; cudaGetSymbolAddress((void**)&q, g_Q);
    float* k; cudaGetSymbolAddress((void**)&k, g_K);
    float* v; cudaGetSymbolAddress((void**)&v, g_V);
    float* o; cudaGetSymbolAddress((void**)&o, g_O);
    __nv_bfloat16 *xhi, *xlo, *wqh, *wql, *wkh, *wkl, *wvh, *wvl, *woh, *wol, *ohi, *olo;
    __nv_bfloat16 *qbh, *qbl, *kbh, *kbl, *vth, *vtl;
    cudaGetSymbolAddress((void**)&xhi, g_Xhi);  cudaGetSymbolAddress((void**)&xlo, g_Xlo);
    cudaGetSymbolAddress((void**)&wqh, g_WqThi); cudaGetSymbolAddress((void**)&wql, g_WqTlo);
    cudaGetSymbolAddress((void**)&wkh, g_WkThi); cudaGetSymbolAddress((void**)&wkl, g_WkTlo);
    cudaGetSymbolAddress((void**)&wvh, g_WvThi); cudaGetSymbolAddress((void**)&wvl, g_WvTlo);
    cudaGetSymbolAddress((void**)&woh, g_WoThi); cudaGetSymbolAddress((void**)&wol, g_WoTlo);
    cudaGetSymbolAddress((void**)&ohi, g_Ohi);   cudaGetSymbolAddress((void**)&olo, g_Olo);
    cudaGetSymbolAddress((void**)&qbh, g_Qbh);   cudaGetSymbolAddress((void**)&qbl, g_Qbl);
    cudaGetSymbolAddress((void**)&kbh, g_Kbh);   cudaGetSymbolAddress((void**)&kbl, g_Kbl);
    cudaGetSymbolAddress((void**)&vth, g_Vth);   cudaGetSymbolAddress((void**)&vtl, g_Vtl);

    cudaFuncSetAttribute(mma_gemm_kernel,
                         cudaFuncAttributeMaxDynamicSharedMemorySize, GEMM_SMEM);
    cudaFuncSetAttribute(attn_mma_kernel,
                         cudaFuncAttributeMaxDynamicSharedMemorySize, ATTN_SMEM);

    // launch 0: split X
    {
        int n4 = (M_ROWS * HID) / 4;
        split_rowmajor_kernel<<<(n4 + 255) / 256, 256>>>(hidden, xhi, xlo, n4);
    }
    // launches 1-3: transpose Wq, Wk, Wv (Wo deferred)
    {
        dim3 gq(HID / 32, HID / 32);
        transpose_split_kernel<<<gq, 256>>>(Wq, wqh, wql, HID, HID);
        dim3 gkv(KVDIM / 32, HID / 32);
        transpose_split_kernel<<<gkv, 256>>>(Wk, wkh, wkl, HID, KVDIM);
        transpose_split_kernel<<<gkv, 256>>>(Wv, wvh, wvl, HID, KVDIM);
    }
    // launch 4 (ncu slot): Q projection GEMM
    {
        dim3 gqk(HID / 128, M_ROWS / 128);
        mma_gemm_kernel<<<gqk, 256, GEMM_SMEM>>>(xhi, xlo, wqh, wql, q, HID, NHEADS, 1);
        dim3 gkv(KVDIM / 128, M_ROWS / 128);
        mma_gemm_kernel<<<gkv, 256, GEMM_SMEM>>>(xhi, xlo, wkh, wkl, k, KVDIM, NKV, 1);
        mma_gemm_kernel<<<gkv, 256, GEMM_SMEM>>>(xhi, xlo, wvh, wvl, v, KVDIM, NKV, 1);
    }
    // RoPE + split to bf16
    {
        int totQ = BATCH * NHEADS * S_LEN * 64;
        int totK = BATCH * NKV * S_LEN * 64;
        float qscale = 1.0f / sqrtf((float)HDIM);
        rope_split_kernel<<<(totQ + 255) / 256, 256>>>(q, qbh, qbl, qscale, totQ);
        rope_split_kernel<<<(totK + 255) / 256, 256>>>(k, kbh, kbl, 1.0f, totK);
    }
    // V transpose + split
    {
        dim3 gv(S_LEN / 32, HDIM / 32, BATCH * NKV);
        transposeV_split_kernel<<<gv, 256>>>(v, vth, vtl);
    }
    // attention (tensor cores)
    {
        dim3 g(S_LEN / 128, NHEADS, BATCH);
        attn_mma_kernel<<<g, 256, ATTN_SMEM>>>();
    }
    // output projection
    {
        int n4 = (M_ROWS * HID) / 4;
        splitO_kernel<<<(n4 + 255) / 256, 256>>>(o, ohi, olo, n4);
        dim3 gq(HID / 32, HID / 32);
        transpose_split_kernel<<<gq, 256>>>(Wo, woh, wol, HID, HID);
        dim3 go(HID / 128, M_ROWS / 128);
        mma_gemm_kernel<<<go, 256, GEMM_SMEM>>>(ohi, olo, woh, wol, out, HID, NHEADS, 0);
    }
}

// round 5
// speedup vs baseline: 3.3947x; 1.0048x over previous
#include <cuda_runtime.h>
#include <cuda_bf16.h>
#include <math.h>
#include <stdint.h>

#define S_LEN   2048
#define BATCH   2
#define NHEADS  32
#define NKV     8
#define HDIM    128
#define HID     4096
#define KVDIM   1024
#define M_ROWS  4096   // B*S
#define WINDOW  512    // SLIDING_WINDOW // 2
#define GK      4096   // GEMM K
#define NC      (GK/64)

// ======================== scratch buffers ==================================
__device__ float g_V[(size_t)BATCH * NKV * S_LEN * HDIM];   // fp32 V [b,hk,s,d]

__device__ __nv_bfloat16 g_Xhi[(size_t)M_ROWS * HID];
__device__ __nv_bfloat16 g_Xlo[(size_t)M_ROWS * HID];
__device__ __nv_bfloat16 g_WqThi[(size_t)HID * HID];
__device__ __nv_bfloat16 g_WqTlo[(size_t)HID * HID];
__device__ __nv_bfloat16 g_WkThi[(size_t)KVDIM * HID];
__device__ __nv_bfloat16 g_WkTlo[(size_t)KVDIM * HID];
__device__ __nv_bfloat16 g_WvThi[(size_t)KVDIM * HID];
__device__ __nv_bfloat16 g_WvTlo[(size_t)KVDIM * HID];
__device__ __nv_bfloat16 g_WoThi[(size_t)HID * HID];
__device__ __nv_bfloat16 g_WoTlo[(size_t)HID * HID];
__device__ __nv_bfloat16 g_Ohi[(size_t)M_ROWS * HID];
__device__ __nv_bfloat16 g_Olo[(size_t)M_ROWS * HID];

// bf16 attention operands (RoPE'd)
__device__ __nv_bfloat16 g_Qbh[(size_t)BATCH * NHEADS * S_LEN * HDIM];
__device__ __nv_bfloat16 g_Qbl[(size_t)BATCH * NHEADS * S_LEN * HDIM];
__device__ __nv_bfloat16 g_Kbh[(size_t)BATCH * NKV * S_LEN * HDIM];
__device__ __nv_bfloat16 g_Kbl[(size_t)BATCH * NKV * S_LEN * HDIM];
__device__ __nv_bfloat16 g_Vth[(size_t)BATCH * NKV * HDIM * S_LEN];  // [b,hk,d,s]
__device__ __nv_bfloat16 g_Vtl[(size_t)BATCH * NKV * HDIM * S_LEN];

// ======================= low-level helpers =================================
__device__ __forceinline__ uint32_t smem_u32(const void* p) {
    uint32_t a;
    asm("{ .reg .u64 t; cvta.to.shared.u64 t, %1; cvt.u32.u64 %0, t; }"
        : "=r"(a) : "l"(p));
    return a;
}
__device__ __forceinline__ void cpasync16(uint32_t saddr, const void* g) {
    asm volatile("cp.async.cg.shared.global [%0], [%1], 16;"
                 :: "r"(saddr), "l"(g) : "memory");
}
#define SWZ(o) ((o) ^ (((o) >> 3) & 0x70))

__device__ __forceinline__ void ldmx4(uint32_t* r, uint32_t addr) {
    asm volatile("ldmatrix.sync.aligned.m8n8.x4.shared.b16 {%0,%1,%2,%3}, [%4];"
                 : "=r"(r[0]), "=r"(r[1]), "=r"(r[2]), "=r"(r[3]) : "r"(addr));
}
__device__ __forceinline__ void ldmx2(uint32_t* r, uint32_t addr) {
    asm volatile("ldmatrix.sync.aligned.m8n8.x2.shared.b16 {%0,%1}, [%2];"
                 : "=r"(r[0]), "=r"(r[1]) : "r"(addr));
}
__device__ __forceinline__ void mma16816(float* d, const uint32_t* a, const uint32_t* b) {
    asm volatile("mma.sync.aligned.m16n8k16.row.col.f32.bf16.bf16.f32 "
                 "{%0,%1,%2,%3}, {%4,%5,%6,%7}, {%8,%9}, {%0,%1,%2,%3};"
                 : "+f"(d[0]), "+f"(d[1]), "+f"(d[2]), "+f"(d[3])
                 : "r"(a[0]), "r"(a[1]), "r"(a[2]), "r"(a[3]),
                   "r"(b[0]), "r"(b[1]));
}

// fast exp on FMA pipe (avoids MUFU throughput wall)
__device__ __forceinline__ float fast_exp(float x) {
    float y = x * 1.4426950408889634f;
    float r = rintf(y);
    float f = y - r;
    float p = 1.3697664e-3f;
    p = fmaf(p, f, 9.6784195e-3f);
    p = fmaf(p, f, 5.5503454e-2f);
    p = fmaf(p, f, 2.4022652e-1f);
    p = fmaf(p, f, 6.9314718e-1f);
    p = fmaf(p, f, 1.0f);
    int ri = (int)r;
    ri = ri < -126 ? -126 : (ri > 126 ? 126 : ri);
    float s = __int_as_float((uint32_t)(ri + 127) << 23);
    return p * s;
}

__device__ __forceinline__ void split1(float f, __nv_bfloat16& h, __nv_bfloat16& l) {
    h = __float2bfloat16_rn(f);
    l = __float2bfloat16_rn(f - __bfloat162float(h));
}

// ===================== split / transpose preprocessing =====================
__global__ void split_rowmajor_kernel(const float* __restrict__ X,
                                      __nv_bfloat16* __restrict__ hi,
                                      __nv_bfloat16* __restrict__ lo, int n4)
{
    int i = blockIdx.x * blockDim.x + threadIdx.x;
    if (i >= n4) return;
    float4 v = reinterpret_cast<const float4*>(X)[i];
    __nv_bfloat16 h0, h1, h2, h3, l0, l1, l2, l3;
    split1(v.x, h0, l0); split1(v.y, h1, l1);
    split1(v.z, h2, l2); split1(v.w, h3, l3);
    __nv_bfloat162* hp = reinterpret_cast<__nv_bfloat162*>(hi) + 2 * i;
    __nv_bfloat162* lp = reinterpret_cast<__nv_bfloat162*>(lo) + 2 * i;
    hp[0] = __halves2bfloat162(h0, h1); hp[1] = __halves2bfloat162(h2, h3);
    lp[0] = __halves2bfloat162(l0, l1); lp[1] = __halves2bfloat162(l2, l3);
}

__global__ void transpose_split_kernel(const float* __restrict__ W,
                                       __nv_bfloat16* __restrict__ hi,
                                       __nv_bfloat16* __restrict__ lo,
                                       int K, int N)
{
    __shared__ float t[32][33];
    int k0 = blockIdx.y * 32, n0 = blockIdx.x * 32;
    int c = threadIdx.x & 31, r = threadIdx.x >> 5;
#pragma unroll
    for (int p = 0; p < 32; p += 8)
        t[r + p][c] = W[(size_t)(k0 + r + p) * N + n0 + c];
    __syncthreads();
#pragma unroll
    for (int p = 0; p < 32; p += 8) {
        float f = t[c][r + p];
        __nv_bfloat16 h, l;
        split1(f, h, l);
        size_t o = (size_t)(n0 + r + p) * K + k0 + c;
        hi[o] = h; lo[o] = l;
    }
}

// g_V [b,hk,s,d] fp32 -> Vt hi/lo [b,hk,d,s] bf16
__global__ void transposeV_split_kernel(const float* __restrict__ V,
                                        __nv_bfloat16* __restrict__ Vth,
                                        __nv_bfloat16* __restrict__ Vtl)
{
    __shared__ float t[32][33];
    int bhk = blockIdx.z;
    int s0 = blockIdx.x * 32, d0 = blockIdx.y * 32;
    const float* src = V + (size_t)bhk * S_LEN * HDIM;
    int c = threadIdx.x & 31, r = threadIdx.x >> 5;
#pragma unroll
    for (int p = 0; p < 32; p += 8)
        t[r + p][c] = src[(size_t)(s0 + r + p) * HDIM + d0 + c];
    __syncthreads();
    size_t dstbase = (size_t)bhk * HDIM * S_LEN;
#pragma unroll
    for (int p = 0; p < 32; p += 8) {
        float f = t[c][r + p];              // = V[s0+c][d0+r+p]
        __nv_bfloat16 h, l;
        split1(f, h, l);
        size_t o = dstbase + (size_t)(d0 + r + p) * S_LEN + s0 + c;
        Vth[o] = h; Vtl[o] = l;
    }
}

// =================== mma.sync bf16-split GEMM ==============================
// C[M,N] = (Ahi+Alo)[M,GK] @ (Bhi+Blo)^T, B stored [N,GK] K-major.
// CTA 128x128, 256 threads (8 warps, 2x4), warp tile 64x32, K-chunk 64.
// EMODE 0: C row-major fp32 [M,N].
// EMODE 1: scatter fp32 to [b,nH,s,d].
// EMODE 2: RoPE (angle from s-row, d) + scale + bf16 hi/lo split,
//          scatter to Chi/Clo [b,nH,s,d]. Tile N=128 = exactly one head.
#define TILE_BYTES  16384
#define STAGE_BYTES (4 * TILE_BYTES)
#define GEMM_SMEM   (3 * STAGE_BYTES)

__device__ __forceinline__ void load_stage_gemm(
    uint32_t stage_base, int tid, int mBase, int nBase, int kb,
    const __nv_bfloat16* __restrict__ Ahi, const __nv_bfloat16* __restrict__ Alo,
    const __nv_bfloat16* __restrict__ Bhi, const __nv_bfloat16* __restrict__ Blo)
{
#pragma unroll
    for (int u = 0; u < 4; ++u) {
        int unit = tid + u * 256;
        int r = unit >> 3, c16 = unit & 7;
        uint32_t soff = (uint32_t)(r * 128 + c16 * 16);
        uint32_t sw = SWZ(soff);
        size_t ga = (size_t)(mBase + r) * GK + kb + c16 * 8;
        size_t gb = (size_t)(nBase + r) * GK + kb + c16 * 8;
        cpasync16(stage_base + sw,                  Ahi + ga);
        cpasync16(stage_base + TILE_BYTES + sw,     Alo + ga);
        cpasync16(stage_base + 2 * TILE_BYTES + sw, Bhi + gb);
        cpasync16(stage_base + 3 * TILE_BYTES + sw, Blo + gb);
    }
    asm volatile("cp.async.commit_group;" ::: "memory");
}

__global__ void __launch_bounds__(256, 1) mma_gemm_kernel(
    const __nv_bfloat16* __restrict__ Ahi, const __nv_bfloat16* __restrict__ Alo,
    const __nv_bfloat16* __restrict__ Bhi, const __nv_bfloat16* __restrict__ Blo,
    float* __restrict__ C,
    __nv_bfloat16* __restrict__ Chi, __nv_bfloat16* __restrict__ Clo,
    float ropeScale, int N, int nH, int EMODE)
{
    extern __shared__ __align__(1024) char smem_raw[];
    const uint32_t sbase = smem_u32(smem_raw);
    const int tid  = threadIdx.x;
    const int wid  = tid >> 5, lane = tid & 31;
    const int wm   = wid >> 2;
    const int wn   = wid & 3;
    const int mBase = blockIdx.y * 128;
    const int nBase = blockIdx.x * 128;

    float acc[4][4][4];
#pragma unroll
    for (int mt = 0; mt < 4; mt++)
#pragma unroll
        for (int nt = 0; nt < 4; nt++)
#pragma unroll
            for (int e = 0; e < 4; e++) acc[mt][nt][e] = 0.f;

    load_stage_gemm(sbase + 0 * STAGE_BYTES, tid, mBase, nBase, 0,   Ahi, Alo, Bhi, Blo);
    load_stage_gemm(sbase + 1 * STAGE_BYTES, tid, mBase, nBase, 64,  Ahi, Alo, Bhi, Blo);
    load_stage_gemm(sbase + 2 * STAGE_BYTES, tid, mBase, nBase, 128, Ahi, Alo, Bhi, Blo);

    const int aRow = wm * 64 + (lane & 15);
    const int aK8  = (lane >> 4);
    const int bRow = wn * 32 + (lane & 7);
    const int bK8  = ((lane >> 3) & 1);

    for (int c2 = 0; c2 < NC; ++c2) {
        if (c2 + 2 < NC)      asm volatile("cp.async.wait_group 2;" ::: "memory");
        else if (c2 + 1 < NC) asm volatile("cp.async.wait_group 1;" ::: "memory");
        else                  asm volatile("cp.async.wait_group 0;" ::: "memory");
        __syncthreads();

        const uint32_t st   = sbase + (c2 % 3) * STAGE_BYTES;
        const uint32_t aHiB = st;
        const uint32_t aLoB = st + TILE_BYTES;
        const uint32_t bHiB = st + 2 * TILE_BYTES;
        const uint32_t bLoB = st + 3 * TILE_BYTES;

#pragma unroll
        for (int ks = 0; ks < 4; ks++) {
            uint32_t bh[4][2], bl[4][2];
            const int bk = ks * 16 + bK8 * 8;
#pragma unroll
            for (int nt = 0; nt < 4; nt++) {
                uint32_t off = (uint32_t)((bRow + nt * 8) * 128 + bk * 2);
                uint32_t sw = SWZ(off);
                ldmx2(bh[nt], bHiB + sw);
                ldmx2(bl[nt], bLoB + sw);
            }
            const int ak = ks * 16 + aK8 * 8;
#pragma unroll
            for (int mt = 0; mt < 4; mt++) {
                uint32_t off = (uint32_t)((aRow + mt * 16) * 128 + ak * 2);
                uint32_t sw = SWZ(off);
                uint32_t ah[4], al[4];
                ldmx4(ah, aHiB + sw);
                ldmx4(al, aLoB + sw);
#pragma unroll
                for (int nt = 0; nt < 4; nt++) {
                    mma16816(acc[mt][nt], ah, bh[nt]);
                    mma16816(acc[mt][nt], ah, bl[nt]);
                    mma16816(acc[mt][nt], al, bh[nt]);
                }
            }
        }
        __syncthreads();
        if (c2 + 3 < NC)
            load_stage_gemm(sbase + (c2 % 3) * STAGE_BYTES, tid, mBase, nBase,
                            (c2 + 3) * 64, Ahi, Alo, Bhi, Blo);
    }

    const int colInTile0 = wn * 32 + (lane & 3) * 2;
    const int row0       = wm * 64 + (lane >> 2);

    if (EMODE == 2) {
        // stage accumulators to smem, then RoPE + split + coalesced write
        float* stage = reinterpret_cast<float*>(smem_raw);   // [128][132]
#pragma unroll
        for (int mt = 0; mt < 4; mt++)
#pragma unroll
            for (int half = 0; half < 2; half++) {
                int r = row0 + mt * 16 + half * 8;
#pragma unroll
                for (int nt = 0; nt < 4; nt++) {
                    int c = colInTile0 + nt * 8;
                    stage[r * 132 + c]     = acc[mt][nt][half * 2];
                    stage[r * 132 + c + 1] = acc[mt][nt][half * 2 + 1];
                }
            }
        __syncthreads();

        const int b = mBase >> 11;
        const int h = nBase >> 7;
        const int sBase = mBase & 2047;
        const size_t headBase = ((size_t)(b * nH + h) * S_LEN) * HDIM;
#pragma unroll
        for (int it = 0; it < 32; it++) {
            int pr = tid + it * 256;          // 0..8191
            int r = pr >> 6, dp = pr & 63;
            float x1 = stage[r * 132 + dp];
            float x2 = stage[r * 132 + dp + 64];
            int srow = sBase + r;
            float inv_freq = exp2f(-(float)dp * (13.287712379549449f / 64.0f));
            float ang = (float)srow * inv_freq;
            float c, sn;
            sincosf(ang, &sn, &c);
            float y1 = (x1 * c - x2 * sn) * ropeScale;
            float y2 = (x2 * c + x1 * sn) * ropeScale;
            size_t base = headBase + (size_t)srow * HDIM;
            __nv_bfloat16 hh, ll;
            split1(y1, hh, ll); Chi[base + dp] = hh;      Clo[base + dp] = ll;
            split1(y2, hh, ll); Chi[base + dp + 64] = hh; Clo[base + dp + 64] = ll;
        }
        return;
    }

#pragma unroll
    for (int mt = 0; mt < 4; mt++) {
#pragma unroll
        for (int half = 0; half < 2; half++) {
            int grow = mBase + row0 + mt * 16 + half * 8;
#pragma unroll
            for (int nt = 0; nt < 4; nt++) {
                int lcol = colInTile0 + nt * 8;
                float2 v = make_float2(acc[mt][nt][half * 2],
                                       acc[mt][nt][half * 2 + 1]);
                if (EMODE == 1) {
                    int b = grow >> 11, srow = grow & 2047;
                    int h = (nBase + lcol) >> 7;
                    int d = lcol & 127;
                    *reinterpret_cast<float2*>(
                        C + (((size_t)(b * nH + h)) * S_LEN + srow) * HDIM + d) = v;
                } else {
                    *reinterpret_cast<float2*>(C + (size_t)grow * N + nBase + lcol) = v;
                }
            }
        }
    }
}

// ================= tensor-core flash attention (bf16 hi/lo) ================
#define AT_STAGE 65536
#define ATTN_SMEM (2 * AT_STAGE)

__global__ void __launch_bounds__(256, 1) attn_mma_kernel()
{
    extern __shared__ __align__(1024) char smem_raw[];
    const uint32_t sb = smem_u32(smem_raw);
    const int tid = threadIdx.x, wid = tid >> 5, lane = tid & 31;
    const int qt = blockIdx.x, h = blockIdx.y, b = blockIdx.z;
    const int hk = h >> 2;
    const int q0 = qt * 128;
    const int bh = b * NHEADS + h, bhk = b * NKV + hk;

    const __nv_bfloat16* Qhg = g_Qbh + ((size_t)bh * S_LEN + q0) * HDIM;
    const __nv_bfloat16* Qlg = g_Qbl + ((size_t)bh * S_LEN + q0) * HDIM;
    const __nv_bfloat16* Khg = g_Kbh + (size_t)bhk * S_LEN * HDIM;
    const __nv_bfloat16* Klg = g_Kbl + (size_t)bhk * S_LEN * HDIM;
    const __nv_bfloat16* Vhg = g_Vth + (size_t)bhk * HDIM * S_LEN;
    const __nv_bfloat16* Vlg = g_Vtl + (size_t)bhk * HDIM * S_LEN;

    // ---- stage Q (hi at sb+0, lo at sb+32768) ----
#pragma unroll
    for (int it = 0; it < 16; it++) {
        int u = tid + it * 256;
        int bf = u >> 11;
        int w  = u & 2047;
        int r = w >> 4, c16 = w & 15;
        int sub = c16 >> 3;
        uint32_t off = (uint32_t)(bf * 32768 + sub * 16384 + r * 128 + (c16 & 7) * 16);
        const __nv_bfloat16* g = (bf ? Qlg : Qhg) + (size_t)r * HDIM + c16 * 8;
        cpasync16(sb + SWZ(off), g);
    }
    asm volatile("cp.async.commit_group;" ::: "memory");
    asm volatile("cp.async.wait_group 0;" ::: "memory");
    __syncthreads();

    uint32_t qh[8][4], ql[8][4];
    {
        int row = wid * 16 + (lane & 15);
        int k8 = lane >> 4;
#pragma unroll
        for (int kf = 0; kf < 8; kf++) {
            int sub = kf >> 2;
            uint32_t off = (uint32_t)(sub * 16384 + row * 128 + ((kf & 3) * 16 + k8 * 8) * 2);
            uint32_t sw = SWZ(off);
            ldmx4(qh[kf], sb + sw);
            ldmx4(ql[kf], sb + 32768 + sw);
        }
    }
    __syncthreads();

    float o[16][4];
#pragma unroll
    for (int nf = 0; nf < 16; nf++)
#pragma unroll
        for (int e = 0; e < 4; e++) o[nf][e] = 0.f;

    float m0 = -1e30f, m1 = -1e30f, l0 = 0.f, l1 = 0.f;
    const int g0row = q0 + wid * 16 + (lane >> 2);

    int kt_lo = 2 * qt - 8; if (kt_lo < 0) kt_lo = 0;
    const int nt = 2 * qt + 1 - kt_lo + 1;

    auto load_kv = [&](int stage, int kt) {
        const int k0 = kt * 64;
        const uint32_t stb = sb + (uint32_t)stage * AT_STAGE;
#pragma unroll
        for (int it = 0; it < 16; it++) {
            int u = tid + it * 256;
            int buf = u >> 10;
            int w = u & 1023;
            int r = w >> 3, c16 = w & 7;
            uint32_t off = (uint32_t)(buf * 16384 + r * 128 + c16 * 16);
            const __nv_bfloat16* g;
            if (buf < 2) {
                int key = r & 63, sub = r >> 6;
                g = (buf ? Klg : Khg) + (size_t)(k0 + key) * HDIM + sub * 64 + c16 * 8;
            } else {
                g = (buf == 3 ? Vlg : Vhg) + (size_t)r * S_LEN + k0 + c16 * 8;
            }
            cpasync16(stb + SWZ(off), g);
        }
        asm volatile("cp.async.commit_group;" ::: "memory");
    };

    load_kv(0, kt_lo);
    load_kv(1, kt_lo + 1);

    for (int i = 0; i < nt; i++) {
        const int kt = kt_lo + i;
        const int k0 = kt * 64;
        if (i + 1 < nt) asm volatile("cp.async.wait_group 1;" ::: "memory");
        else            asm volatile("cp.async.wait_group 0;" ::: "memory");
        __syncthreads();
        const uint32_t stb = sb + (uint32_t)(i & 1) * AT_STAGE;

        // ---- S = Q K^T (3-pass) ----
        float s[8][4];
#pragma unroll
        for (int nf = 0; nf < 8; nf++)
#pragma unroll
            for (int e = 0; e < 4; e++) s[nf][e] = 0.f;

#pragma unroll
        for (int kf = 0; kf < 8; kf++) {
            const int sub = kf >> 2;
            const int klocal = (kf & 3) * 16;
            uint32_t kbh[8][2], kbl[8][2];
#pragma unroll
            for (int np = 0; np < 4; np++) {
                int m = lane >> 3;
                int nf2 = np * 2 + (m >> 1);
                int key = nf2 * 8 + (lane & 7);
                int dl = klocal + (m & 1) * 8;
                uint32_t off = (uint32_t)((sub * 64 + key) * 128 + dl * 2);
                uint32_t sw = SWZ(off);
                uint32_t r4[4];
                ldmx4(r4, stb + sw);
                kbh[np * 2][0] = r4[0]; kbh[np * 2][1] = r4[1];
                kbh[np * 2 + 1][0] = r4[2]; kbh[np * 2 + 1][1] = r4[3];
                ldmx4(r4, stb + 16384 + sw);
                kbl[np * 2][0] = r4[0]; kbl[np * 2][1] = r4[1];
                kbl[np * 2 + 1][0] = r4[2]; kbl[np * 2 + 1][1] = r4[3];
            }
#pragma unroll
            for (int nf = 0; nf < 8; nf++) {
                mma16816(s[nf], qh[kf], kbh[nf]);
                mma16816(s[nf], qh[kf], kbl[nf]);
                mma16816(s[nf], ql[kf], kbh[nf]);
            }
        }

        // ---- mask (boundary tiles only) ----
        if ((k0 + 63 > q0) || (q0 + 127 - k0 > WINDOW)) {
#pragma unroll
            for (int nf = 0; nf < 8; nf++)
#pragma unroll
                for (int e = 0; e < 4; e++) {
                    int row = g0row + ((e >= 2) ? 8 : 0);
                    int col = k0 + nf * 8 + (lane & 3) * 2 + (e & 1);
                    if (col > row || row - col > WINDOW) s[nf][e] = -1e30f;
                }
        }

        // ---- streaming softmax (in-warp) ----
        float mx0 = -1e30f, mx1 = -1e30f;
#pragma unroll
        for (int nf = 0; nf < 8; nf++) {
            mx0 = fmaxf(mx0, fmaxf(s[nf][0], s[nf][1]));
            mx1 = fmaxf(mx1, fmaxf(s[nf][2], s[nf][3]));
        }
        mx0 = fmaxf(mx0, __shfl_xor_sync(0xffffffffu, mx0, 1));
        mx0 = fmaxf(mx0, __shfl_xor_sync(0xffffffffu, mx0, 2));
        mx1 = fmaxf(mx1, __shfl_xor_sync(0xffffffffu, mx1, 1));
        mx1 = fmaxf(mx1, __shfl_xor_sync(0xffffffffu, mx1, 2));
        float mn0 = fmaxf(m0, mx0), mn1 = fmaxf(m1, mx1);
        float fac0 = fast_exp(m0 - mn0), fac1 = fast_exp(m1 - mn1);
        m0 = mn0; m1 = mn1;

        uint32_t ph[8][2], pl[8][2];
        float ps0 = 0.f, ps1 = 0.f;
#pragma unroll
        for (int nf = 0; nf < 8; nf++) {
            float p0 = fast_exp(s[nf][0] - mn0);
            float p1 = fast_exp(s[nf][1] - mn0);
            float p2 = fast_exp(s[nf][2] - mn1);
            float p3 = fast_exp(s[nf][3] - mn1);
            ps0 += p0 + p1; ps1 += p2 + p3;
            __nv_bfloat16 h0, lo0, h1, lo1, h2, lo2, h3, lo3;
            split1(p0, h0, lo0); split1(p1, h1, lo1);
            split1(p2, h2, lo2); split1(p3, h3, lo3);
            __nv_bfloat162 t;
            t = __halves2bfloat162(h0, h1);  ph[nf][0] = *reinterpret_cast<uint32_t*>(&t);
            t = __halves2bfloat162(h2, h3);  ph[nf][1] = *reinterpret_cast<uint32_t*>(&t);
            t = __halves2bfloat162(lo0, lo1); pl[nf][0] = *reinterpret_cast<uint32_t*>(&t);
            t = __halves2bfloat162(lo2, lo3); pl[nf][1] = *reinterpret_cast<uint32_t*>(&t);
        }
        ps0 += __shfl_xor_sync(0xffffffffu, ps0, 1);
        ps0 += __shfl_xor_sync(0xffffffffu, ps0, 2);
        ps1 += __shfl_xor_sync(0xffffffffu, ps1, 1);
        ps1 += __shfl_xor_sync(0xffffffffu, ps1, 2);
        l0 = l0 * fac0 + ps0;
        l1 = l1 * fac1 + ps1;

#pragma unroll
        for (int nf = 0; nf < 16; nf++) {
            o[nf][0] *= fac0; o[nf][1] *= fac0;
            o[nf][2] *= fac1; o[nf][3] *= fac1;
        }

        // ---- O += P @ Vt (3-pass) ----
#pragma unroll
        for (int kf2 = 0; kf2 < 4; kf2++) {
            uint32_t pah[4] = { ph[2 * kf2][0], ph[2 * kf2][1],
                                ph[2 * kf2 + 1][0], ph[2 * kf2 + 1][1] };
            uint32_t pal[4] = { pl[2 * kf2][0], pl[2 * kf2][1],
                                pl[2 * kf2 + 1][0], pl[2 * kf2 + 1][1] };
#pragma unroll
            for (int np = 0; np < 8; np++) {
                int m = lane >> 3;
                int drow = (np * 2 + (m >> 1)) * 8 + (lane & 7);
                int kl = kf2 * 16 + (m & 1) * 8;
                uint32_t off = (uint32_t)(32768 + drow * 128 + kl * 2);
                uint32_t sw = SWZ(off);
                uint32_t r4[4], r4l[4];
                ldmx4(r4,  stb + sw);
                ldmx4(r4l, stb + 16384 + sw);
                uint32_t vb0[2] = { r4[0], r4[1] },  vb1[2] = { r4[2], r4[3] };
                uint32_t vl0[2] = { r4l[0], r4l[1] }, vl1[2] = { r4l[2], r4l[3] };
                mma16816(o[np * 2],     pah, vb0);
                mma16816(o[np * 2],     pah, vl0);
                mma16816(o[np * 2],     pal, vb0);
                mma16816(o[np * 2 + 1], pah, vb1);
                mma16816(o[np * 2 + 1], pah, vl1);
                mma16816(o[np * 2 + 1], pal, vb1);
            }
        }
        __syncthreads();
        if (i + 2 < nt) load_kv(i & 1, kt + 2);
    }

    // ---- write O directly as bf16 hi/lo row-major [m, h*128+d] ----
    const float inv0 = 1.f / l0, inv1 = 1.f / l1;
    const int r0 = wid * 16 + (lane >> 2);
    const int c0 = (lane & 3) * 2;
    const size_t rowA = ((size_t)(b * S_LEN + q0 + r0)) * HID + h * HDIM;
    const size_t rowB = ((size_t)(b * S_LEN + q0 + r0 + 8)) * HID + h * HDIM;
#pragma unroll
    for (int nf = 0; nf < 16; nf++) {
        int d = nf * 8 + c0;
        __nv_bfloat16 h0, l0b, h1, l1b;
        split1(o[nf][0] * inv0, h0, l0b);
        split1(o[nf][1] * inv0, h1, l1b);
        __nv_bfloat162 th = __halves2bfloat162(h0, h1);
        __nv_bfloat162 tl = __halves2bfloat162(l0b, l1b);
        *reinterpret_cast<__nv_bfloat162*>(g_Ohi + rowA + d) = th;
        *reinterpret_cast<__nv_bfloat162*>(g_Olo + rowA + d) = tl;
        split1(o[nf][2] * inv1, h0, l0b);
        split1(o[nf][3] * inv1, h1, l1b);
        th = __halves2bfloat162(h0, h1);
        tl = __halves2bfloat162(l0b, l1b);
        *reinterpret_cast<__nv_bfloat162*>(g_Ohi + rowB + d) = th;
        *reinterpret_cast<__nv_bfloat162*>(g_Olo + rowB + d) = tl;
    }
}

// ---------------------------------------------------------------------------
extern "C" void kernel_launch(void* const* d_in, const int* in_sizes, int n_in,
                              void* d_out, int out_size)
{
    (void)in_sizes; (void)n_in; (void)out_size;
    const float* hidden = (const float*)d_in[0];
    const float* Wq     = (const float*)d_in[1];
    const float* Wk     = (const float*)d_in[2];
    const float* Wv     = (const float*)d_in[3];
    const float* Wo     = (const float*)d_in[4];
    float* out          = (float*)d_out;

    float* v; cudaGetSymbolAddress((void**)&v, g_V);
    __nv_bfloat16 *xhi, *xlo, *wqh, *wql, *wkh, *wkl, *wvh, *wvl, *woh, *wol, *ohi, *olo;
    __nv_bfloat16 *qbh, *qbl, *kbh, *kbl, *vth, *vtl;
    cudaGetSymbolAddress((void**)&xhi, g_Xhi);  cudaGetSymbolAddress((void**)&xlo, g_Xlo);
    cudaGetSymbolAddress((void**)&wqh, g_WqThi); cudaGetSymbolAddress((void**)&wql, g_WqTlo);
    cudaGetSymbolAddress((void**)&wkh, g_WkThi); cudaGetSymbolAddress((void**)&wkl, g_WkTlo);
    cudaGetSymbolAddress((void**)&wvh, g_WvThi); cudaGetSymbolAddress((void**)&wvl, g_WvTlo);
    cudaGetSymbolAddress((void**)&woh, g_WoThi); cudaGetSymbolAddress((void**)&wol, g_WoTlo);
    cudaGetSymbolAddress((void**)&ohi, g_Ohi);   cudaGetSymbolAddress((void**)&olo, g_Olo);
    cudaGetSymbolAddress((void**)&qbh, g_Qbh);   cudaGetSymbolAddress((void**)&qbl, g_Qbl);
    cudaGetSymbolAddress((void**)&kbh, g_Kbh);   cudaGetSymbolAddress((void**)&kbl, g_Kbl);
    cudaGetSymbolAddress((void**)&vth, g_Vth);   cudaGetSymbolAddress((void**)&vtl, g_Vtl);

    cudaFuncSetAttribute(mma_gemm_kernel,
                         cudaFuncAttributeMaxDynamicSharedMemorySize, GEMM_SMEM);
    cudaFuncSetAttribute(attn_mma_kernel,
                         cudaFuncAttributeMaxDynamicSharedMemorySize, ATTN_SMEM);

    const float qscale = 1.0f / sqrtf((float)HDIM);

    // 0: transpose Wq
    {
        dim3 gq(HID / 32, HID / 32);
        transpose_split_kernel<<<gq, 256>>>(Wq, wqh, wql, HID, HID);
    }
    // 1: split X
    {
        int n4 = (M_ROWS * HID) / 4;
        split_rowmajor_kernel<<<(n4 + 255) / 256, 256>>>(hidden, xhi, xlo, n4);
    }
    // 2: Q projection (+RoPE +scale +split)
    {
        dim3 g(HID / 128, M_ROWS / 128);
        mma_gemm_kernel<<<g, 256, GEMM_SMEM>>>(xhi, xlo, wqh, wql,
                                               nullptr, qbh, qbl, qscale,
                                               HID, NHEADS, 2);
    }
    // 3: transpose Wk,  4: K projection (+RoPE +split)
    {
        dim3 gkv(KVDIM / 32, HID / 32);
        transpose_split_kernel<<<gkv, 256>>>(Wk, wkh, wkl, HID, KVDIM);
        dim3 g(KVDIM / 128, M_ROWS / 128);
        mma_gemm_kernel<<<g, 256, GEMM_SMEM>>>(xhi, xlo, wkh, wkl,
                                               nullptr, kbh, kbl, 1.0f,
                                               KVDIM, NKV, 2);
    }
    // 5: transpose Wv,  6: V projection (fp32 scatter), 7: transpose V
    {
        dim3 gkv(KVDIM / 32, HID / 32);
        transpose_split_kernel<<<gkv, 256>>>(Wv, wvh, wvl, HID, KVDIM);
        dim3 g(KVDIM / 128, M_ROWS / 128);
        mma_gemm_kernel<<<g, 256, GEMM_SMEM>>>(xhi, xlo, wvh, wvl,
                                               v, nullptr, nullptr, 0.f,
                                               KVDIM, NKV, 1);
        dim3 gv(S_LEN / 32, HDIM / 32, BATCH * NKV);
        transposeV_split_kernel<<<gv, 256>>>(v, vth, vtl);
    }
    // 8: attention (writes Ohi/Olo bf16 directly)
    {
        dim3 g(S_LEN / 128, NHEADS, BATCH);
        attn_mma_kernel<<<g, 256, ATTN_SMEM>>>();
    }
    // 9: transpose Wo, 10: output projection
    {
        dim3 gq(HID / 32, HID / 32);
        transpose_split_kernel<<<gq, 256>>>(Wo, woh, wol, HID, HID);
        dim3 go(HID / 128, M_ROWS / 128);
        mma_gemm_kernel<<<go, 256, GEMM_SMEM>>>(ohi, olo, woh, wol,
                                                out, nullptr, nullptr, 0.f,
                                                HID, NHEADS, 0);
    }
}